// round 10
// baseline (speedup 1.0000x reference)
#include <cuda_runtime.h>
#include <cuda_fp16.h>
#include <cstdint>

#define Bdim 8
#define Sdim 512
#define Hdim 768
#define Ldim 8192

// scratch (static device globals: allocation-free)
__device__ __half g_xh[Bdim * Sdim * Hdim];                 // inputs as fp16
__device__ __half g_xth[Bdim * Hdim * Sdim];                // inputs^T [B,H,S] fp16
__device__ __half g_eh[Ldim * Hdim];                        // label_embedding fp16
__device__ __half g_wh[Hdim * Hdim];                        // W_key fp16
__device__ __half g_akh[Bdim * Sdim * Hdim];                // attn_key fp16
__device__ int    g_mask_is_i32;

// ---------------- PTX helpers ----------------
__device__ __forceinline__ void mma_f16(float* c, const uint32_t* a, const uint32_t* b) {
    asm volatile(
        "mma.sync.aligned.m16n8k16.row.col.f32.f16.f16.f32 "
        "{%0,%1,%2,%3}, {%4,%5,%6,%7}, {%8,%9}, {%0,%1,%2,%3};\n"
        : "+f"(c[0]), "+f"(c[1]), "+f"(c[2]), "+f"(c[3])
        : "r"(a[0]), "r"(a[1]), "r"(a[2]), "r"(a[3]), "r"(b[0]), "r"(b[1]));
}

__device__ __forceinline__ void ldsm_x4(uint32_t& r0, uint32_t& r1, uint32_t& r2,
                                        uint32_t& r3, uint32_t addr) {
    asm volatile("ldmatrix.sync.aligned.m8n8.x4.shared.b16 {%0,%1,%2,%3}, [%4];"
                 : "=r"(r0), "=r"(r1), "=r"(r2), "=r"(r3) : "r"(addr));
}

__device__ __forceinline__ void cp16(uint32_t s, const void* g) {
    asm volatile("cp.async.cg.shared.global [%0], [%1], 16;\n" :: "r"(s), "l"(g));
}
__device__ __forceinline__ void cp_commit() { asm volatile("cp.async.commit_group;\n"); }
__device__ __forceinline__ void cp_wait1()  { asm volatile("cp.async.wait_group 1;\n"); }
__device__ __forceinline__ void cp_wait0()  { asm volatile("cp.async.wait_group 0;\n"); }

// ---------------- prep: fp32 -> fp16 ----------------
__global__ void k_cvt(const float4* __restrict__ src, uint4* __restrict__ dst, int n8) {
    int i = blockIdx.x * blockDim.x + threadIdx.x;
    int stride = gridDim.x * blockDim.x;
    for (; i < n8; i += stride) {
        float4 a = src[2 * i], b = src[2 * i + 1];
        __half2 h0 = __floats2half2_rn(a.x, a.y);
        __half2 h1 = __floats2half2_rn(a.z, a.w);
        __half2 h2 = __floats2half2_rn(b.x, b.y);
        __half2 h3 = __floats2half2_rn(b.z, b.w);
        uint4 o;
        o.x = *(uint32_t*)&h0; o.y = *(uint32_t*)&h1;
        o.z = *(uint32_t*)&h2; o.w = *(uint32_t*)&h3;
        dst[i] = o;
    }
}

// transpose+convert: XT[b][h][s] = half(X[b][s][h])
__global__ void k_trh(const float* __restrict__ X, __half* __restrict__ XT) {
    __shared__ float t[32][33];
    int b = blockIdx.z;
    int s0 = blockIdx.y * 32, h0 = blockIdx.x * 32;
    int x = threadIdx.x, y = threadIdx.y;  // 32 x 8
    const float* src = X + ((size_t)b * Sdim + s0) * Hdim + h0;
#pragma unroll
    for (int i = 0; i < 32; i += 8)
        t[y + i][x] = src[(size_t)(y + i) * Hdim + x];
    __syncthreads();
    __half* dst = XT + ((size_t)b * Hdim + h0) * Sdim + s0;
#pragma unroll
    for (int i = 0; i < 32; i += 8)
        dst[(size_t)(y + i) * Sdim + x] = __float2half_rn(t[x][y + i]);
}

// ---------------- mask dtype detection ----------------
__global__ void k_detect(const int* __restrict__ m) {
    __shared__ int bad;
    if (threadIdx.x == 0) bad = 0;
    __syncthreads();
    int local = 0;
#pragma unroll
    for (int i = 0; i < 4; i++) {
        unsigned v = (unsigned)m[threadIdx.x + i * 256];
        if (v > 1u) local = 1;
    }
    if (local) atomicOr(&bad, 1);
    __syncthreads();
    if (threadIdx.x == 0) g_mask_is_i32 = bad ? 0 : 1;
}

// Row stride in halves (80B): LDSM rows hit distinct 16B segs mod 128 -> conflict-free
#define RS 40

// ---------------- Kernel 1: attn_key = inputs @ W_key^T ----------------
// BM=128 BN=128 BK=32, 256 threads (warps 2x4, WM=64 WN=32), 2-stage
__global__ __launch_bounds__(256) void k_keyproj(const __half* __restrict__ A,
                                                 const __half* __restrict__ W) {
    extern __shared__ __align__(16) float smem[];
    uint32_t sb  = (uint32_t)__cvta_generic_to_shared(smem);
    const uint32_t sbA = sb;
    const uint32_t sbB = sb + 2u * 128u * RS * 2u;

    const int tid  = threadIdx.x;
    const int lane = tid & 31, wid = tid >> 5;
    const int wm = wid & 1, wn = wid >> 1;
    const int tg = lane & 3, gid = lane >> 2;
    const int m0 = blockIdx.y * 128, n0 = blockIdx.x * 128;

    const int a_row = lane & 15, a_kh = (lane >> 4) << 3;
    const int b_row = ((lane >> 4) << 3) + (lane & 7), b_kh = ((lane >> 3) & 1) << 3;

    float acc[4][4][4];
#pragma unroll
    for (int i = 0; i < 4; i++)
#pragma unroll
        for (int j = 0; j < 4; j++)
#pragma unroll
            for (int r = 0; r < 4; r++) acc[i][j][r] = 0.f;

#pragma unroll
    for (int i = 0; i < 2; i++) {
        int idx = tid + i * 256;
        int r = idx >> 2, c = (idx & 3) * 8;
        cp16(sbA + (uint32_t)(r * RS + c) * 2u, A + (size_t)(m0 + r) * Hdim + c);
        cp16(sbB + (uint32_t)(r * RS + c) * 2u, W + (size_t)(n0 + r) * Hdim + c);
    }
    cp_commit();

    const int KT = Hdim / 32;  // 24
#pragma unroll 1
    for (int kt = 0; kt < KT; ++kt) {
        int cur = kt & 1;
        if (kt + 1 < KT) {
            int nxt = cur ^ 1;
#pragma unroll
            for (int i = 0; i < 2; i++) {
                int idx = tid + i * 256;
                int r = idx >> 2, c = (idx & 3) * 8;
                cp16(sbA + (uint32_t)(nxt * 128 * RS + r * RS + c) * 2u,
                     A + (size_t)(m0 + r) * Hdim + (kt + 1) * 32 + c);
                cp16(sbB + (uint32_t)(nxt * 128 * RS + r * RS + c) * 2u,
                     W + (size_t)(n0 + r) * Hdim + (kt + 1) * 32 + c);
            }
            cp_commit();
            cp_wait1();
        } else {
            cp_wait0();
        }
        __syncthreads();
        const uint32_t aBase = sbA + (uint32_t)(cur * 128 * RS) * 2u;
        const uint32_t bBase = sbB + (uint32_t)(cur * 128 * RS) * 2u;
#pragma unroll
        for (int kk = 0; kk < 2; ++kk) {
            uint32_t af[4][4], bf[4][2];
#pragma unroll
            for (int mt = 0; mt < 4; ++mt)
                ldsm_x4(af[mt][0], af[mt][1], af[mt][2], af[mt][3],
                        aBase + (uint32_t)(((wm * 64 + mt * 16 + a_row) * RS + kk * 16 + a_kh) * 2));
#pragma unroll
            for (int p = 0; p < 2; ++p)
                ldsm_x4(bf[2 * p][0], bf[2 * p][1], bf[2 * p + 1][0], bf[2 * p + 1][1],
                        bBase + (uint32_t)(((wn * 32 + p * 16 + b_row) * RS + kk * 16 + b_kh) * 2));
#pragma unroll
            for (int mt = 0; mt < 4; ++mt)
#pragma unroll
                for (int nt = 0; nt < 4; ++nt)
                    mma_f16(acc[mt][nt], af[mt], bf[nt]);
        }
        __syncthreads();
    }
#pragma unroll
    for (int mt = 0; mt < 4; ++mt) {
        int r = m0 + wm * 64 + mt * 16 + gid;
#pragma unroll
        for (int nt = 0; nt < 4; ++nt) {
            int c = n0 + wn * 32 + nt * 8 + tg * 2;
            *(__half2*)(&g_akh[(size_t)r * Hdim + c]) =
                __floats2half2_rn(acc[mt][nt][0], acc[mt][nt][1]);
            *(__half2*)(&g_akh[(size_t)(r + 8) * Hdim + c]) =
                __floats2half2_rn(acc[mt][nt][2], acc[mt][nt][3]);
        }
    }
}

// ---------------- Fused Kernel: softmax(mask(E@AK^T)) @ X ------------------
// Per CTA: 64 labels x batch b. 512 threads, warps 2x8.
// Phase 1: scores 64x512 (BK=32, 3-stage, WN=64), masked softmax, probs->smem.
// Phase 2: out[64,768] = probs @ X, H split 2x384 (WN=48), XT streamed 3-stage.
#define P_RS 520
#define F_ASTG (64 * RS)
#define F_BSTG (512 * RS)
#define F_B_OFF (3 * F_ASTG)
#define F_XT_OFF (64 * P_RS)
#define F_XTSTG (384 * RS)
#define F_RED_BYTE (2 * (F_XT_OFF + 3 * F_XTSTG))
#define F_SMEM_BYTES (F_RED_BYTE + 64 * 8 * 4 + 512 + 256)

__global__ __launch_bounds__(512) void k_fused(const __half* __restrict__ E,
                                               const __half* __restrict__ XT,
                                               const void* __restrict__ masks,
                                               float* __restrict__ O) {
    extern __shared__ __align__(16) float smem[];
    uint32_t sb = (uint32_t)__cvta_generic_to_shared(smem);
    float* red = (float*)((char*)smem + F_RED_BYTE);
    unsigned char* msk = (unsigned char*)red + 64 * 8 * 4;

    const int tid  = threadIdx.x;
    const int lane = tid & 31, wid = tid >> 5;
    const int wm = wid & 1, wn = wid >> 1;  // 2 x 8
    const int tg = lane & 3, gid = lane >> 2;
    const int b  = blockIdx.y;
    const int m0 = blockIdx.x * 64;
    const __half* Bt = g_akh + (size_t)b * Sdim * Hdim;

    const int a_row = lane & 15, a_kh = (lane >> 4) << 3;
    const int b_row = ((lane >> 4) << 3) + (lane & 7), b_kh = ((lane >> 3) & 1) << 3;

    {   // mask -> smem
        int is32 = g_mask_is_i32;
        unsigned v = is32 ? (unsigned)((const int*)masks)[b * Sdim + tid]
                          : (unsigned)((const unsigned char*)masks)[b * Sdim + tid];
        msk[tid] = v ? 1 : 0;
    }

    const uint32_t sbA = sb;
    const uint32_t sbB = sb + (uint32_t)F_B_OFF * 2u;

    // ================= Phase 1: scores + softmax =================
    float acc[2][8][4];
#pragma unroll
    for (int i = 0; i < 2; i++)
#pragma unroll
        for (int j = 0; j < 8; j++)
#pragma unroll
            for (int r = 0; r < 4; r++) acc[i][j][r] = 0.f;

    auto fill1 = [&](int st, int kt) {
        if (tid < 256) {  // A: 64 x 32 halves = 256 cp16
            int r = tid >> 2, c = (tid & 3) * 8;
            cp16(sbA + (uint32_t)(st * F_ASTG + r * RS + c) * 2u,
                 E + (size_t)(m0 + r) * Hdim + kt * 32 + c);
        }
#pragma unroll
        for (int i = 0; i < 4; i++) {  // B: 512 x 32 halves = 2048 cp16
            int idx = tid + i * 512;
            int r = idx >> 2, c = (idx & 3) * 8;
            cp16(sbB + (uint32_t)(st * F_BSTG + r * RS + c) * 2u,
                 Bt + (size_t)r * Hdim + kt * 32 + c);
        }
        cp_commit();
    };

    const int KT = Hdim / 32;  // 24
    fill1(0, 0);
    fill1(1, 1);
    cp_wait1();
    __syncthreads();

#pragma unroll 1
    for (int kt = 0; kt < KT; ++kt) {
        int cur = kt % 3;
        const uint32_t aBase = sbA + (uint32_t)(cur * F_ASTG) * 2u;
        const uint32_t bBase = sbB + (uint32_t)(cur * F_BSTG) * 2u;
#pragma unroll
        for (int kk = 0; kk < 2; ++kk) {
            uint32_t af[2][4], bf[8][2];
#pragma unroll
            for (int mt = 0; mt < 2; ++mt)
                ldsm_x4(af[mt][0], af[mt][1], af[mt][2], af[mt][3],
                        aBase + (uint32_t)(((wm * 32 + mt * 16 + a_row) * RS + kk * 16 + a_kh) * 2));
#pragma unroll
            for (int p = 0; p < 4; ++p)
                ldsm_x4(bf[2 * p][0], bf[2 * p][1], bf[2 * p + 1][0], bf[2 * p + 1][1],
                        bBase + (uint32_t)(((wn * 64 + p * 16 + b_row) * RS + kk * 16 + b_kh) * 2));
#pragma unroll
            for (int mt = 0; mt < 2; ++mt)
#pragma unroll
                for (int nt = 0; nt < 8; ++nt)
                    mma_f16(acc[mt][nt], af[mt], bf[nt]);
        }
        if (kt + 2 < KT) fill1((kt + 2) % 3, kt + 2);
        if (kt + 1 < KT) { if (kt + 2 < KT) cp_wait1(); else cp_wait0(); }
        __syncthreads();
    }

    // masked softmax (fp32)
    float mx[4] = {-1e30f, -1e30f, -1e30f, -1e30f};
#pragma unroll
    for (int mt = 0; mt < 2; ++mt)
#pragma unroll
        for (int nt = 0; nt < 8; ++nt) {
            int col = wn * 64 + nt * 8 + tg * 2;
            bool m0ok = msk[col] != 0, m1ok = msk[col + 1] != 0;
            if (!m0ok) { acc[mt][nt][0] = -1e30f; acc[mt][nt][2] = -1e30f; }
            if (!m1ok) { acc[mt][nt][1] = -1e30f; acc[mt][nt][3] = -1e30f; }
            mx[mt * 2]     = fmaxf(mx[mt * 2],     fmaxf(acc[mt][nt][0], acc[mt][nt][1]));
            mx[mt * 2 + 1] = fmaxf(mx[mt * 2 + 1], fmaxf(acc[mt][nt][2], acc[mt][nt][3]));
        }
#pragma unroll
    for (int j = 0; j < 4; ++j) {
        mx[j] = fmaxf(mx[j], __shfl_xor_sync(0xffffffffu, mx[j], 1));
        mx[j] = fmaxf(mx[j], __shfl_xor_sync(0xffffffffu, mx[j], 2));
    }
    if (tg == 0) {
#pragma unroll
        for (int j = 0; j < 4; ++j) {
            int rl = wm * 32 + (j >> 1) * 16 + (j & 1) * 8 + gid;
            red[rl * 8 + wn] = mx[j];
        }
    }
    __syncthreads();
    float gmx[4];
#pragma unroll
    for (int j = 0; j < 4; ++j) {
        int rl = wm * 32 + (j >> 1) * 16 + (j & 1) * 8 + gid;
        float m = -1e30f;
#pragma unroll
        for (int w = 0; w < 8; ++w) m = fmaxf(m, red[rl * 8 + w]);
        gmx[j] = m;
    }
    __syncthreads();

    float sme[4] = {0.f, 0.f, 0.f, 0.f};
#pragma unroll
    for (int mt = 0; mt < 2; ++mt)
#pragma unroll
        for (int nt = 0; nt < 8; ++nt) {
            float e0 = __expf(acc[mt][nt][0] - gmx[mt * 2]);
            float e1 = __expf(acc[mt][nt][1] - gmx[mt * 2]);
            float e2 = __expf(acc[mt][nt][2] - gmx[mt * 2 + 1]);
            float e3 = __expf(acc[mt][nt][3] - gmx[mt * 2 + 1]);
            acc[mt][nt][0] = e0; acc[mt][nt][1] = e1;
            acc[mt][nt][2] = e2; acc[mt][nt][3] = e3;
            sme[mt * 2]     += e0 + e1;
            sme[mt * 2 + 1] += e2 + e3;
        }
#pragma unroll
    for (int j = 0; j < 4; ++j) {
        sme[j] += __shfl_xor_sync(0xffffffffu, sme[j], 1);
        sme[j] += __shfl_xor_sync(0xffffffffu, sme[j], 2);
    }
    if (tg == 0) {
#pragma unroll
        for (int j = 0; j < 4; ++j) {
            int rl = wm * 32 + (j >> 1) * 16 + (j & 1) * 8 + gid;
            red[rl * 8 + wn] = sme[j];
        }
    }
    __syncthreads();
    float inv[4];
#pragma unroll
    for (int j = 0; j < 4; ++j) {
        int rl = wm * 32 + (j >> 1) * 16 + (j & 1) * 8 + gid;
        float s = 0.f;
#pragma unroll
        for (int w = 0; w < 8; ++w) s += red[rl * 8 + w];
        inv[j] = 1.f / s;
    }

    // probs -> smem fp16 (aliases dead phase-1 stages)
    __half* probs = (__half*)smem;
#pragma unroll
    for (int mt = 0; mt < 2; ++mt) {
        int r0 = wm * 32 + mt * 16 + gid;
        int r1 = r0 + 8;
#pragma unroll
        for (int nt = 0; nt < 8; ++nt) {
            int col = wn * 64 + nt * 8 + tg * 2;
            *(__half2*)(&probs[r0 * P_RS + col]) =
                __floats2half2_rn(acc[mt][nt][0] * inv[mt * 2], acc[mt][nt][1] * inv[mt * 2]);
            *(__half2*)(&probs[r1 * P_RS + col]) =
                __floats2half2_rn(acc[mt][nt][2] * inv[mt * 2 + 1], acc[mt][nt][3] * inv[mt * 2 + 1]);
        }
    }
    __syncthreads();

    // ================= Phase 2: out = probs @ X =================
    const uint32_t pB   = sb;                               // probs base
    const uint32_t sbXT = sb + (uint32_t)F_XT_OFF * 2u;

#pragma unroll 1
    for (int ht = 0; ht < 2; ++ht) {
        const __half* Xg = XT + ((size_t)b * Hdim + ht * 384) * Sdim;

        float acc2[2][6][4];
#pragma unroll
        for (int i = 0; i < 2; i++)
#pragma unroll
            for (int j = 0; j < 6; j++)
#pragma unroll
                for (int r = 0; r < 4; r++) acc2[i][j][r] = 0.f;

        auto fill2 = [&](int st, int kt) {
#pragma unroll
            for (int i = 0; i < 3; i++) {  // 384 x 32 halves = 1536 cp16
                int idx = tid + i * 512;
                int r = idx >> 2, c = (idx & 3) * 8;
                cp16(sbXT + (uint32_t)(st * F_XTSTG + r * RS + c) * 2u,
                     Xg + (size_t)r * Sdim + kt * 32 + c);
            }
            cp_commit();
        };

        const int KT2 = Sdim / 32;  // 16
        fill2(0, 0);
        fill2(1, 1);
        cp_wait1();
        __syncthreads();

#pragma unroll 1
        for (int kt = 0; kt < KT2; ++kt) {
            int cur = kt % 3;
            const uint32_t xBase = sbXT + (uint32_t)(cur * F_XTSTG) * 2u;
#pragma unroll
            for (int kk = 0; kk < 2; ++kk) {
                uint32_t af[2][4], bf[6][2];
#pragma unroll
                for (int mt = 0; mt < 2; ++mt)
                    ldsm_x4(af[mt][0], af[mt][1], af[mt][2], af[mt][3],
                            pB + (uint32_t)(((wm * 32 + mt * 16 + a_row) * P_RS +
                                             kt * 32 + kk * 16 + a_kh) * 2));
#pragma unroll
                for (int p = 0; p < 3; ++p)
                    ldsm_x4(bf[2 * p][0], bf[2 * p][1], bf[2 * p + 1][0], bf[2 * p + 1][1],
                            xBase + (uint32_t)(((wn * 48 + p * 16 + b_row) * RS + kk * 16 + b_kh) * 2));
#pragma unroll
                for (int mt = 0; mt < 2; ++mt)
#pragma unroll
                    for (int nt = 0; nt < 6; ++nt)
                        mma_f16(acc2[mt][nt], af[mt], bf[nt]);
            }
            if (kt + 2 < KT2) fill2((kt + 2) % 3, kt + 2);
            if (kt + 1 < KT2) { if (kt + 2 < KT2) cp_wait1(); else cp_wait0(); }
            __syncthreads();
        }

        // epilogue: write this H-half
#pragma unroll
        for (int mt = 0; mt < 2; ++mt) {
            int r = m0 + wm * 32 + mt * 16 + gid;
            size_t base0 = ((size_t)b * Ldim + r) * Hdim;
            size_t base1 = ((size_t)b * Ldim + r + 8) * Hdim;
#pragma unroll
            for (int nt = 0; nt < 6; ++nt) {
                int c = ht * 384 + wn * 48 + nt * 8 + tg * 2;
                *(float2*)(&O[base0 + c]) = make_float2(acc2[mt][nt][0], acc2[mt][nt][1]);
                *(float2*)(&O[base1 + c]) = make_float2(acc2[mt][nt][2], acc2[mt][nt][3]);
            }
        }
    }
}

// ---------------- launcher ----------------
#define K1_SMEM_BYTES (4 * 128 * RS * 2)

extern "C" void kernel_launch(void* const* d_in, const int* in_sizes, int n_in,
                              void* d_out, int out_size) {
    const float* inputs = (const float*)d_in[0];
    const void*  masks  = d_in[1];
    const float* emb    = (const float*)d_in[2];
    const float* wkey   = (const float*)d_in[3];
    float* out = (float*)d_out;
    (void)in_sizes; (void)n_in; (void)out_size;

    cudaFuncSetAttribute(k_keyproj, cudaFuncAttributeMaxDynamicSharedMemorySize, K1_SMEM_BYTES);
    cudaFuncSetAttribute(k_fused,   cudaFuncAttributeMaxDynamicSharedMemorySize, F_SMEM_BYTES);

    __half* d_xh;  cudaGetSymbolAddress((void**)&d_xh,  g_xh);
    __half* d_xth; cudaGetSymbolAddress((void**)&d_xth, g_xth);
    __half* d_eh;  cudaGetSymbolAddress((void**)&d_eh,  g_eh);
    __half* d_wh;  cudaGetSymbolAddress((void**)&d_wh,  g_wh);

    k_detect<<<1, 256>>>((const int*)masks);
    k_cvt<<<512, 256>>>((const float4*)inputs, (uint4*)d_xh, Bdim * Sdim * Hdim / 8);
    k_cvt<<<512, 256>>>((const float4*)emb,    (uint4*)d_eh, Ldim * Hdim / 8);
    k_cvt<<<256, 256>>>((const float4*)wkey,   (uint4*)d_wh, Hdim * Hdim / 8);
    k_trh<<<dim3(Hdim / 32, Sdim / 32, Bdim), dim3(32, 8)>>>(inputs, d_xth);
    k_keyproj<<<dim3(6, 32, 1), 256, K1_SMEM_BYTES>>>(d_xh, d_wh);
    k_fused<<<dim3(Ldim / 64, Bdim), 512, F_SMEM_BYTES>>>(d_eh, d_xth, masks, out);
}

// round 11
// speedup vs baseline: 1.0609x; 1.0609x over previous
#include <cuda_runtime.h>
#include <cuda_fp16.h>
#include <cstdint>

#define Bdim 8
#define Sdim 512
#define Hdim 768
#define Ldim 8192

// scratch (static device globals: allocation-free)
__device__ __half g_xh[Bdim * Sdim * Hdim];                 // inputs as fp16
__device__ __half g_xth[Bdim * Hdim * Sdim];                // compacted inputs^T [B,H,j] fp16
__device__ __half g_eh[Ldim * Hdim];                        // label_embedding fp16
__device__ __half g_wh[Hdim * Hdim];                        // W_key fp16
__device__ __half g_akh[Bdim * Sdim * Hdim];                // attn_key fp16 (full S)
__device__ int    g_idx[Bdim * Sdim];                       // compaction index per batch
__device__ int    g_nv[Bdim];                               // valid count per batch
__device__ int    g_mask_is_i32;

// ---------------- PTX helpers ----------------
__device__ __forceinline__ void mma_f16(float* c, const uint32_t* a, const uint32_t* b) {
    asm volatile(
        "mma.sync.aligned.m16n8k16.row.col.f32.f16.f16.f32 "
        "{%0,%1,%2,%3}, {%4,%5,%6,%7}, {%8,%9}, {%0,%1,%2,%3};\n"
        : "+f"(c[0]), "+f"(c[1]), "+f"(c[2]), "+f"(c[3])
        : "r"(a[0]), "r"(a[1]), "r"(a[2]), "r"(a[3]), "r"(b[0]), "r"(b[1]));
}

__device__ __forceinline__ void ldsm_x4(uint32_t& r0, uint32_t& r1, uint32_t& r2,
                                        uint32_t& r3, uint32_t addr) {
    asm volatile("ldmatrix.sync.aligned.m8n8.x4.shared.b16 {%0,%1,%2,%3}, [%4];"
                 : "=r"(r0), "=r"(r1), "=r"(r2), "=r"(r3) : "r"(addr));
}

__device__ __forceinline__ void cp16(uint32_t s, const void* g) {
    asm volatile("cp.async.cg.shared.global [%0], [%1], 16;\n" :: "r"(s), "l"(g));
}
__device__ __forceinline__ void cp_commit() { asm volatile("cp.async.commit_group;\n"); }
__device__ __forceinline__ void cp_wait1()  { asm volatile("cp.async.wait_group 1;\n"); }
__device__ __forceinline__ void cp_wait0()  { asm volatile("cp.async.wait_group 0;\n"); }

// ---------------- prep: fp32 -> fp16 ----------------
__global__ void k_cvt(const float4* __restrict__ src, uint4* __restrict__ dst, int n8) {
    int i = blockIdx.x * blockDim.x + threadIdx.x;
    int stride = gridDim.x * blockDim.x;
    for (; i < n8; i += stride) {
        float4 a = src[2 * i], b = src[2 * i + 1];
        __half2 h0 = __floats2half2_rn(a.x, a.y);
        __half2 h1 = __floats2half2_rn(a.z, a.w);
        __half2 h2 = __floats2half2_rn(b.x, b.y);
        __half2 h3 = __floats2half2_rn(b.z, b.w);
        uint4 o;
        o.x = *(uint32_t*)&h0; o.y = *(uint32_t*)&h1;
        o.z = *(uint32_t*)&h2; o.w = *(uint32_t*)&h3;
        dst[i] = o;
    }
}

// ---------------- mask dtype detection ----------------
__global__ void k_detect(const int* __restrict__ m) {
    __shared__ int bad;
    if (threadIdx.x == 0) bad = 0;
    __syncthreads();
    int local = 0;
#pragma unroll
    for (int i = 0; i < 4; i++) {
        unsigned v = (unsigned)m[threadIdx.x + i * 256];
        if (v > 1u) local = 1;
    }
    if (local) atomicOr(&bad, 1);
    __syncthreads();
    if (threadIdx.x == 0) g_mask_is_i32 = bad ? 0 : 1;
}

// ---------------- mask scan: build compaction index ----------------
__global__ void k_scan(const void* __restrict__ masks) {
    __shared__ int sc[512];
    int b = blockIdx.x, t = threadIdx.x;
    int is32 = g_mask_is_i32;
    unsigned v = is32 ? (unsigned)((const int*)masks)[b * Sdim + t]
                      : (unsigned)((const unsigned char*)masks)[b * Sdim + t];
    int m = v ? 1 : 0;
    sc[t] = m;
    __syncthreads();
    for (int off = 1; off < 512; off <<= 1) {
        int x = (t >= off) ? sc[t - off] : 0;
        __syncthreads();
        sc[t] += x;
        __syncthreads();
    }
    int nv = sc[511];
    if (m) g_idx[b * Sdim + sc[t] - 1] = t;
    if (t >= nv) g_idx[b * Sdim + t] = 0;
    if (t == 0) g_nv[b] = nv;
}

// gather+transpose+convert: XTc[b][h][j] = half(X[b][idx[j]][h])
__global__ void k_gtr(const float* __restrict__ X, __half* __restrict__ XT) {
    __shared__ float t[32][33];
    int b = blockIdx.z;
    int j0 = blockIdx.y * 32, h0 = blockIdx.x * 32;
    int x = threadIdx.x, y = threadIdx.y;  // 32 x 8
    const float* srcb = X + (size_t)b * Sdim * Hdim;
#pragma unroll
    for (int i = 0; i < 32; i += 8) {
        int s = g_idx[b * Sdim + j0 + y + i];
        t[y + i][x] = srcb[(size_t)s * Hdim + h0 + x];
    }
    __syncthreads();
    __half* dst = XT + ((size_t)b * Hdim + h0) * Sdim + j0;
#pragma unroll
    for (int i = 0; i < 32; i += 8)
        dst[(size_t)(y + i) * Sdim + x] = __float2half_rn(t[x][y + i]);
}

// Row stride in halves (80B): LDSM rows hit distinct 16B segs mod 128 -> conflict-free
#define RS 40

// ---------------- Kernel 1: attn_key = inputs @ W_key^T ----------------
// BM=128 BN=128 BK=32, 256 threads (warps 2x4, WM=64 WN=32), 2-stage
__global__ __launch_bounds__(256) void k_keyproj(const __half* __restrict__ A,
                                                 const __half* __restrict__ W) {
    extern __shared__ __align__(16) float smem[];
    uint32_t sb  = (uint32_t)__cvta_generic_to_shared(smem);
    const uint32_t sbA = sb;
    const uint32_t sbB = sb + 2u * 128u * RS * 2u;

    const int tid  = threadIdx.x;
    const int lane = tid & 31, wid = tid >> 5;
    const int wm = wid & 1, wn = wid >> 1;
    const int tg = lane & 3, gid = lane >> 2;
    const int m0 = blockIdx.y * 128, n0 = blockIdx.x * 128;

    const int a_row = lane & 15, a_kh = (lane >> 4) << 3;
    const int b_row = ((lane >> 4) << 3) + (lane & 7), b_kh = ((lane >> 3) & 1) << 3;

    float acc[4][4][4];
#pragma unroll
    for (int i = 0; i < 4; i++)
#pragma unroll
        for (int j = 0; j < 4; j++)
#pragma unroll
            for (int r = 0; r < 4; r++) acc[i][j][r] = 0.f;

#pragma unroll
    for (int i = 0; i < 2; i++) {
        int idx = tid + i * 256;
        int r = idx >> 2, c = (idx & 3) * 8;
        cp16(sbA + (uint32_t)(r * RS + c) * 2u, A + (size_t)(m0 + r) * Hdim + c);
        cp16(sbB + (uint32_t)(r * RS + c) * 2u, W + (size_t)(n0 + r) * Hdim + c);
    }
    cp_commit();

    const int KT = Hdim / 32;  // 24
#pragma unroll 1
    for (int kt = 0; kt < KT; ++kt) {
        int cur = kt & 1;
        if (kt + 1 < KT) {
            int nxt = cur ^ 1;
#pragma unroll
            for (int i = 0; i < 2; i++) {
                int idx = tid + i * 256;
                int r = idx >> 2, c = (idx & 3) * 8;
                cp16(sbA + (uint32_t)(nxt * 128 * RS + r * RS + c) * 2u,
                     A + (size_t)(m0 + r) * Hdim + (kt + 1) * 32 + c);
                cp16(sbB + (uint32_t)(nxt * 128 * RS + r * RS + c) * 2u,
                     W + (size_t)(n0 + r) * Hdim + (kt + 1) * 32 + c);
            }
            cp_commit();
            cp_wait1();
        } else {
            cp_wait0();
        }
        __syncthreads();
        const uint32_t aBase = sbA + (uint32_t)(cur * 128 * RS) * 2u;
        const uint32_t bBase = sbB + (uint32_t)(cur * 128 * RS) * 2u;
#pragma unroll
        for (int kk = 0; kk < 2; ++kk) {
            uint32_t af[4][4], bf[4][2];
#pragma unroll
            for (int mt = 0; mt < 4; ++mt)
                ldsm_x4(af[mt][0], af[mt][1], af[mt][2], af[mt][3],
                        aBase + (uint32_t)(((wm * 64 + mt * 16 + a_row) * RS + kk * 16 + a_kh) * 2));
#pragma unroll
            for (int p = 0; p < 2; ++p)
                ldsm_x4(bf[2 * p][0], bf[2 * p][1], bf[2 * p + 1][0], bf[2 * p + 1][1],
                        bBase + (uint32_t)(((wn * 32 + p * 16 + b_row) * RS + kk * 16 + b_kh) * 2));
#pragma unroll
            for (int mt = 0; mt < 4; ++mt)
#pragma unroll
                for (int nt = 0; nt < 4; ++nt)
                    mma_f16(acc[mt][nt], af[mt], bf[nt]);
        }
        __syncthreads();
    }
#pragma unroll
    for (int mt = 0; mt < 4; ++mt) {
        int r = m0 + wm * 64 + mt * 16 + gid;
#pragma unroll
        for (int nt = 0; nt < 4; ++nt) {
            int c = n0 + wn * 32 + nt * 8 + tg * 2;
            *(__half2*)(&g_akh[(size_t)r * Hdim + c]) =
                __floats2half2_rn(acc[mt][nt][0], acc[mt][nt][1]);
            *(__half2*)(&g_akh[(size_t)(r + 8) * Hdim + c]) =
                __floats2half2_rn(acc[mt][nt][2], acc[mt][nt][3]);
        }
    }
}

// ---------------- Fused Kernel (compacted S) ------------------
// Per CTA: 64 labels x batch b. 256 threads, warps 2x4.
// Phase 1: scores 64 x nv (gathered attn_key rows), softmax, probs -> smem.
// Phase 2: out[64,768] = probs @ Xc, K-loop over ceil(nv/32), H split 2x384.
#define P_RS 520
#define F_ASTG (64 * RS)
#define F_BSTG (512 * RS)
#define F_B_OFF (3 * F_ASTG)
#define F_XT_OFF (64 * P_RS)
#define F_XTSTG (384 * RS)
#define F_RED_BYTE (2 * (F_XT_OFF + 3 * F_XTSTG))
#define F_IDX_BYTE (F_RED_BYTE + 64 * 4 * 4)
#define F_SMEM_BYTES (F_IDX_BYTE + 512 * 4 + 16)

__global__ __launch_bounds__(256) void k_fused(const __half* __restrict__ E,
                                               const __half* __restrict__ XT,
                                               float* __restrict__ O) {
    extern __shared__ __align__(16) float smem[];
    uint32_t sb = (uint32_t)__cvta_generic_to_shared(smem);
    float* red = (float*)((char*)smem + F_RED_BYTE);
    int* sidx  = (int*)((char*)smem + F_IDX_BYTE);

    const int tid  = threadIdx.x;
    const int lane = tid & 31, wid = tid >> 5;
    const int wm = wid & 1, wn = wid >> 1;  // 2 x 4
    const int tg = lane & 3, gid = lane >> 2;
    const int b  = blockIdx.y;
    const int m0 = blockIdx.x * 64;
    const __half* Bt = g_akh + (size_t)b * Sdim * Hdim;
    const int nv = g_nv[b];

    const int a_row = lane & 15, a_kh = (lane >> 4) << 3;
    const int b_row = ((lane >> 4) << 3) + (lane & 7), b_kh = ((lane >> 3) & 1) << 3;

    // stage compaction index into smem
    sidx[tid]       = g_idx[b * Sdim + tid];
    sidx[tid + 256] = g_idx[b * Sdim + tid + 256];
    __syncthreads();

    const uint32_t sbA = sb;
    const uint32_t sbB = sb + (uint32_t)F_B_OFF * 2u;

    // ================= Phase 1: scores + softmax =================
    float acc[2][16][4];
#pragma unroll
    for (int i = 0; i < 2; i++)
#pragma unroll
        for (int j = 0; j < 16; j++)
#pragma unroll
            for (int r = 0; r < 4; r++) acc[i][j][r] = 0.f;

    auto fill1 = [&](int st, int kt) {
        {   // A: 64 x 32 halves = 256 cp16
            int r = tid >> 2, c = (tid & 3) * 8;
            cp16(sbA + (uint32_t)(st * F_ASTG + r * RS + c) * 2u,
                 E + (size_t)(m0 + r) * Hdim + kt * 32 + c);
        }
#pragma unroll
        for (int i = 0; i < 8; i++) {  // B: nv x 32 halves (gathered rows)
            int idx = tid + i * 256;
            int r = idx >> 2, c = (idx & 3) * 8;
            if (r < nv)
                cp16(sbB + (uint32_t)(st * F_BSTG + r * RS + c) * 2u,
                     Bt + (size_t)sidx[r] * Hdim + kt * 32 + c);
        }
        cp_commit();
    };

    const int KT = Hdim / 32;  // 24
    fill1(0, 0);
    fill1(1, 1);
    cp_wait1();
    __syncthreads();

#pragma unroll 1
    for (int kt = 0; kt < KT; ++kt) {
        int cur = kt % 3;
        const uint32_t aBase = sbA + (uint32_t)(cur * F_ASTG) * 2u;
        const uint32_t bBase = sbB + (uint32_t)(cur * F_BSTG) * 2u;
#pragma unroll
        for (int kk = 0; kk < 2; ++kk) {
            uint32_t af[2][4], bf[16][2];
#pragma unroll
            for (int mt = 0; mt < 2; ++mt)
                ldsm_x4(af[mt][0], af[mt][1], af[mt][2], af[mt][3],
                        aBase + (uint32_t)(((wm * 32 + mt * 16 + a_row) * RS + kk * 16 + a_kh) * 2));
#pragma unroll
            for (int p = 0; p < 8; ++p) {
                if (wn * 128 + p * 16 < nv) {
                    ldsm_x4(bf[2 * p][0], bf[2 * p][1], bf[2 * p + 1][0], bf[2 * p + 1][1],
                            bBase + (uint32_t)(((wn * 128 + p * 16 + b_row) * RS + kk * 16 + b_kh) * 2));
#pragma unroll
                    for (int mt = 0; mt < 2; ++mt) {
                        mma_f16(acc[mt][2 * p],     af[mt], bf[2 * p]);
                        mma_f16(acc[mt][2 * p + 1], af[mt], bf[2 * p + 1]);
                    }
                }
            }
        }
        if (kt + 2 < KT) fill1((kt + 2) % 3, kt + 2);
        if (kt + 1 < KT) { if (kt + 2 < KT) cp_wait1(); else cp_wait0(); }
        __syncthreads();
    }

    // softmax over compacted columns (valid = col < nv)
    float mx[4] = {-1e30f, -1e30f, -1e30f, -1e30f};
#pragma unroll
    for (int mt = 0; mt < 2; ++mt)
#pragma unroll
        for (int nt = 0; nt < 16; ++nt) {
            int col = wn * 128 + nt * 8 + tg * 2;
            if (col >= nv)     { acc[mt][nt][0] = -1e30f; acc[mt][nt][2] = -1e30f; }
            if (col + 1 >= nv) { acc[mt][nt][1] = -1e30f; acc[mt][nt][3] = -1e30f; }
            mx[mt * 2]     = fmaxf(mx[mt * 2],     fmaxf(acc[mt][nt][0], acc[mt][nt][1]));
            mx[mt * 2 + 1] = fmaxf(mx[mt * 2 + 1], fmaxf(acc[mt][nt][2], acc[mt][nt][3]));
        }
#pragma unroll
    for (int j = 0; j < 4; ++j) {
        mx[j] = fmaxf(mx[j], __shfl_xor_sync(0xffffffffu, mx[j], 1));
        mx[j] = fmaxf(mx[j], __shfl_xor_sync(0xffffffffu, mx[j], 2));
    }
    if (tg == 0) {
#pragma unroll
        for (int j = 0; j < 4; ++j) {
            int rl = wm * 32 + (j >> 1) * 16 + (j & 1) * 8 + gid;
            red[rl * 4 + wn] = mx[j];
        }
    }
    __syncthreads();
    float gmx[4];
#pragma unroll
    for (int j = 0; j < 4; ++j) {
        int rl = wm * 32 + (j >> 1) * 16 + (j & 1) * 8 + gid;
        float m = -1e30f;
#pragma unroll
        for (int w = 0; w < 4; ++w) m = fmaxf(m, red[rl * 4 + w]);
        gmx[j] = m;
    }
    __syncthreads();

    float sme[4] = {0.f, 0.f, 0.f, 0.f};
#pragma unroll
    for (int mt = 0; mt < 2; ++mt)
#pragma unroll
        for (int nt = 0; nt < 16; ++nt) {
            float e0 = __expf(acc[mt][nt][0] - gmx[mt * 2]);
            float e1 = __expf(acc[mt][nt][1] - gmx[mt * 2]);
            float e2 = __expf(acc[mt][nt][2] - gmx[mt * 2 + 1]);
            float e3 = __expf(acc[mt][nt][3] - gmx[mt * 2 + 1]);
            acc[mt][nt][0] = e0; acc[mt][nt][1] = e1;
            acc[mt][nt][2] = e2; acc[mt][nt][3] = e3;
            sme[mt * 2]     += e0 + e1;
            sme[mt * 2 + 1] += e2 + e3;
        }
#pragma unroll
    for (int j = 0; j < 4; ++j) {
        sme[j] += __shfl_xor_sync(0xffffffffu, sme[j], 1);
        sme[j] += __shfl_xor_sync(0xffffffffu, sme[j], 2);
    }
    if (tg == 0) {
#pragma unroll
        for (int j = 0; j < 4; ++j) {
            int rl = wm * 32 + (j >> 1) * 16 + (j & 1) * 8 + gid;
            red[rl * 4 + wn] = sme[j];
        }
    }
    __syncthreads();
    float inv[4];
#pragma unroll
    for (int j = 0; j < 4; ++j) {
        int rl = wm * 32 + (j >> 1) * 16 + (j & 1) * 8 + gid;
        float s = 0.f;
#pragma unroll
        for (int w = 0; w < 4; ++w) s += red[rl * 4 + w];
        inv[j] = 1.f / s;
    }

    // probs -> smem fp16 (aliases dead phase-1 stages); masked cols are exactly 0
    __half* probs = (__half*)smem;
#pragma unroll
    for (int mt = 0; mt < 2; ++mt) {
        int r0 = wm * 32 + mt * 16 + gid;
        int r1 = r0 + 8;
#pragma unroll
        for (int nt = 0; nt < 16; ++nt) {
            int col = wn * 128 + nt * 8 + tg * 2;
            *(__half2*)(&probs[r0 * P_RS + col]) =
                __floats2half2_rn(acc[mt][nt][0] * inv[mt * 2], acc[mt][nt][1] * inv[mt * 2]);
            *(__half2*)(&probs[r1 * P_RS + col]) =
                __floats2half2_rn(acc[mt][nt][2] * inv[mt * 2 + 1], acc[mt][nt][3] * inv[mt * 2 + 1]);
        }
    }
    __syncthreads();

    // ================= Phase 2: out = probs @ Xc (K = nv, compacted) ========
    const uint32_t pB   = sb;                               // probs base
    const uint32_t sbXT = sb + (uint32_t)F_XT_OFF * 2u;
    const int KT2 = (nv + 31) >> 5;                         // dynamic K chunks

#pragma unroll 1
    for (int ht = 0; ht < 2; ++ht) {
        const __half* Xg = XT + ((size_t)b * Hdim + ht * 384) * Sdim;

        float acc2[2][12][4];
#pragma unroll
        for (int i = 0; i < 2; i++)
#pragma unroll
            for (int j = 0; j < 12; j++)
#pragma unroll
                for (int r = 0; r < 4; r++) acc2[i][j][r] = 0.f;

        auto fill2 = [&](int st, int kt) {
#pragma unroll
            for (int i = 0; i < 6; i++) {  // 384 x 32 halves = 1536 cp16
                int idx = tid + i * 256;
                int r = idx >> 2, c = (idx & 3) * 8;
                cp16(sbXT + (uint32_t)(st * F_XTSTG + r * RS + c) * 2u,
                     Xg + (size_t)r * Sdim + kt * 32 + c);
            }
            cp_commit();
        };

        fill2(0, 0);
        fill2(1, 1);
        cp_wait1();
        __syncthreads();

#pragma unroll 1
        for (int kt = 0; kt < KT2; ++kt) {
            int cur = kt % 3;
            const uint32_t xBase = sbXT + (uint32_t)(cur * F_XTSTG) * 2u;
#pragma unroll
            for (int kk = 0; kk < 2; ++kk) {
                uint32_t af[2][4], bf[12][2];
#pragma unroll
                for (int mt = 0; mt < 2; ++mt)
                    ldsm_x4(af[mt][0], af[mt][1], af[mt][2], af[mt][3],
                            pB + (uint32_t)(((wm * 32 + mt * 16 + a_row) * P_RS +
                                             kt * 32 + kk * 16 + a_kh) * 2));
#pragma unroll
                for (int p = 0; p < 6; ++p)
                    ldsm_x4(bf[2 * p][0], bf[2 * p][1], bf[2 * p + 1][0], bf[2 * p + 1][1],
                            xBase + (uint32_t)(((wn * 96 + p * 16 + b_row) * RS + kk * 16 + b_kh) * 2));
#pragma unroll
                for (int mt = 0; mt < 2; ++mt)
#pragma unroll
                    for (int nt = 0; nt < 12; ++nt)
                        mma_f16(acc2[mt][nt], af[mt], bf[nt]);
            }
            if (kt + 2 < KT2) fill2((kt + 2) % 3, kt + 2);
            if (kt + 1 < KT2) { if (kt + 2 < KT2) cp_wait1(); else cp_wait0(); }
            __syncthreads();
        }

        // epilogue: write this H-half
#pragma unroll
        for (int mt = 0; mt < 2; ++mt) {
            int r = m0 + wm * 32 + mt * 16 + gid;
            size_t base0 = ((size_t)b * Ldim + r) * Hdim;
            size_t base1 = ((size_t)b * Ldim + r + 8) * Hdim;
#pragma unroll
            for (int nt = 0; nt < 12; ++nt) {
                int c = ht * 384 + wn * 96 + nt * 8 + tg * 2;
                *(float2*)(&O[base0 + c]) = make_float2(acc2[mt][nt][0], acc2[mt][nt][1]);
                *(float2*)(&O[base1 + c]) = make_float2(acc2[mt][nt][2], acc2[mt][nt][3]);
            }
        }
    }
}

// ---------------- launcher ----------------
#define K1_SMEM_BYTES (4 * 128 * RS * 2)

extern "C" void kernel_launch(void* const* d_in, const int* in_sizes, int n_in,
                              void* d_out, int out_size) {
    const float* inputs = (const float*)d_in[0];
    const void*  masks  = d_in[1];
    const float* emb    = (const float*)d_in[2];
    const float* wkey   = (const float*)d_in[3];
    float* out = (float*)d_out;
    (void)in_sizes; (void)n_in; (void)out_size;

    cudaFuncSetAttribute(k_keyproj, cudaFuncAttributeMaxDynamicSharedMemorySize, K1_SMEM_BYTES);
    cudaFuncSetAttribute(k_fused,   cudaFuncAttributeMaxDynamicSharedMemorySize, F_SMEM_BYTES);

    __half* d_xh;  cudaGetSymbolAddress((void**)&d_xh,  g_xh);
    __half* d_xth; cudaGetSymbolAddress((void**)&d_xth, g_xth);
    __half* d_eh;  cudaGetSymbolAddress((void**)&d_eh,  g_eh);
    __half* d_wh;  cudaGetSymbolAddress((void**)&d_wh,  g_wh);

    k_detect<<<1, 256>>>((const int*)masks);
    k_scan<<<Bdim, 512>>>(masks);
    k_cvt<<<512, 256>>>((const float4*)inputs, (uint4*)d_xh, Bdim * Sdim * Hdim / 8);
    k_cvt<<<512, 256>>>((const float4*)emb,    (uint4*)d_eh, Ldim * Hdim / 8);
    k_cvt<<<256, 256>>>((const float4*)wkey,   (uint4*)d_wh, Hdim * Hdim / 8);
    k_gtr<<<dim3(Hdim / 32, Sdim / 32, Bdim), dim3(32, 8)>>>(inputs, d_xth);
    k_keyproj<<<dim3(6, 32, 1), 256, K1_SMEM_BYTES>>>(d_xh, d_wh);
    k_fused<<<dim3(Ldim / 64, Bdim), 256, F_SMEM_BYTES>>>(d_eh, d_xth, out);
}

// round 12
// speedup vs baseline: 1.1562x; 1.0898x over previous
#include <cuda_runtime.h>
#include <cuda_fp16.h>
#include <cstdint>

#define Bdim 8
#define Sdim 512
#define Hdim 768
#define Ldim 8192

// scratch (static device globals: allocation-free)
__device__ __half g_xh[Bdim * Sdim * Hdim];                 // inputs as fp16
__device__ __half g_xth[Bdim * Hdim * Sdim];                // compacted inputs^T [B,H,j] fp16
__device__ __half g_eh[Ldim * Hdim];                        // label_embedding fp16
__device__ __half g_wh[Hdim * Hdim];                        // W_key fp16
__device__ __half g_akh[Bdim * Sdim * Hdim];                // attn_key fp16 (full S)
__device__ int    g_idx[Bdim * Sdim];                       // compaction index per batch
__device__ int    g_nv[Bdim];                               // valid count per batch
__device__ int    g_mask_is_i32;

// ---------------- PTX helpers ----------------
__device__ __forceinline__ void mma_f16(float* c, const uint32_t* a, const uint32_t* b) {
    asm volatile(
        "mma.sync.aligned.m16n8k16.row.col.f32.f16.f16.f32 "
        "{%0,%1,%2,%3}, {%4,%5,%6,%7}, {%8,%9}, {%0,%1,%2,%3};\n"
        : "+f"(c[0]), "+f"(c[1]), "+f"(c[2]), "+f"(c[3])
        : "r"(a[0]), "r"(a[1]), "r"(a[2]), "r"(a[3]), "r"(b[0]), "r"(b[1]));
}

__device__ __forceinline__ void ldsm_x4(uint32_t& r0, uint32_t& r1, uint32_t& r2,
                                        uint32_t& r3, uint32_t addr) {
    asm volatile("ldmatrix.sync.aligned.m8n8.x4.shared.b16 {%0,%1,%2,%3}, [%4];"
                 : "=r"(r0), "=r"(r1), "=r"(r2), "=r"(r3) : "r"(addr));
}

__device__ __forceinline__ void cp16(uint32_t s, const void* g) {
    asm volatile("cp.async.cg.shared.global [%0], [%1], 16;\n" :: "r"(s), "l"(g));
}
__device__ __forceinline__ void cp_commit() { asm volatile("cp.async.commit_group;\n"); }
__device__ __forceinline__ void cp_wait1()  { asm volatile("cp.async.wait_group 1;\n"); }
__device__ __forceinline__ void cp_wait0()  { asm volatile("cp.async.wait_group 0;\n"); }

// ---------------- prep: fp32 -> fp16 ----------------
__global__ void k_cvt(const float4* __restrict__ src, uint4* __restrict__ dst, int n8) {
    int i = blockIdx.x * blockDim.x + threadIdx.x;
    int stride = gridDim.x * blockDim.x;
    for (; i < n8; i += stride) {
        float4 a = src[2 * i], b = src[2 * i + 1];
        __half2 h0 = __floats2half2_rn(a.x, a.y);
        __half2 h1 = __floats2half2_rn(a.z, a.w);
        __half2 h2 = __floats2half2_rn(b.x, b.y);
        __half2 h3 = __floats2half2_rn(b.z, b.w);
        uint4 o;
        o.x = *(uint32_t*)&h0; o.y = *(uint32_t*)&h1;
        o.z = *(uint32_t*)&h2; o.w = *(uint32_t*)&h3;
        dst[i] = o;
    }
}

// ---------------- mask dtype detection ----------------
__global__ void k_detect(const int* __restrict__ m) {
    __shared__ int bad;
    if (threadIdx.x == 0) bad = 0;
    __syncthreads();
    int local = 0;
#pragma unroll
    for (int i = 0; i < 4; i++) {
        unsigned v = (unsigned)m[threadIdx.x + i * 256];
        if (v > 1u) local = 1;
    }
    if (local) atomicOr(&bad, 1);
    __syncthreads();
    if (threadIdx.x == 0) g_mask_is_i32 = bad ? 0 : 1;
}

// ---------------- mask scan: build compaction index ----------------
__global__ void k_scan(const void* __restrict__ masks) {
    __shared__ int sc[512];
    int b = blockIdx.x, t = threadIdx.x;
    int is32 = g_mask_is_i32;
    unsigned v = is32 ? (unsigned)((const int*)masks)[b * Sdim + t]
                      : (unsigned)((const unsigned char*)masks)[b * Sdim + t];
    int m = v ? 1 : 0;
    sc[t] = m;
    __syncthreads();
    for (int off = 1; off < 512; off <<= 1) {
        int x = (t >= off) ? sc[t - off] : 0;
        __syncthreads();
        sc[t] += x;
        __syncthreads();
    }
    int nv = sc[511];
    if (m) g_idx[b * Sdim + sc[t] - 1] = t;
    if (t >= nv) g_idx[b * Sdim + t] = 0;
    if (t == 0) g_nv[b] = nv;
}

// gather+transpose+convert: XTc[b][h][j] = half(X[b][idx[j]][h])
__global__ void k_gtr(const float* __restrict__ X, __half* __restrict__ XT) {
    __shared__ float t[32][33];
    int b = blockIdx.z;
    int j0 = blockIdx.y * 32, h0 = blockIdx.x * 32;
    int x = threadIdx.x, y = threadIdx.y;  // 32 x 8
    const float* srcb = X + (size_t)b * Sdim * Hdim;
#pragma unroll
    for (int i = 0; i < 32; i += 8) {
        int s = g_idx[b * Sdim + j0 + y + i];
        t[y + i][x] = srcb[(size_t)s * Hdim + h0 + x];
    }
    __syncthreads();
    __half* dst = XT + ((size_t)b * Hdim + h0) * Sdim + j0;
#pragma unroll
    for (int i = 0; i < 32; i += 8)
        dst[(size_t)(y + i) * Sdim + x] = __float2half_rn(t[x][y + i]);
}

// Row stride in halves (80B): LDSM rows hit distinct 16B segs mod 128 -> conflict-free
#define RS 40

// ---------------- Kernel 1: attn_key = inputs @ W_key^T ----------------
// BM=128 BN=128 BK=32, 256 threads (warps 2x4, WM=64 WN=32), 2-stage
__global__ __launch_bounds__(256) void k_keyproj(const __half* __restrict__ A,
                                                 const __half* __restrict__ W) {
    extern __shared__ __align__(16) float smem[];
    uint32_t sb  = (uint32_t)__cvta_generic_to_shared(smem);
    const uint32_t sbA = sb;
    const uint32_t sbB = sb + 2u * 128u * RS * 2u;

    const int tid  = threadIdx.x;
    const int lane = tid & 31, wid = tid >> 5;
    const int wm = wid & 1, wn = wid >> 1;
    const int tg = lane & 3, gid = lane >> 2;
    const int m0 = blockIdx.y * 128, n0 = blockIdx.x * 128;

    const int a_row = lane & 15, a_kh = (lane >> 4) << 3;
    const int b_row = ((lane >> 4) << 3) + (lane & 7), b_kh = ((lane >> 3) & 1) << 3;

    float acc[4][4][4];
#pragma unroll
    for (int i = 0; i < 4; i++)
#pragma unroll
        for (int j = 0; j < 4; j++)
#pragma unroll
            for (int r = 0; r < 4; r++) acc[i][j][r] = 0.f;

#pragma unroll
    for (int i = 0; i < 2; i++) {
        int idx = tid + i * 256;
        int r = idx >> 2, c = (idx & 3) * 8;
        cp16(sbA + (uint32_t)(r * RS + c) * 2u, A + (size_t)(m0 + r) * Hdim + c);
        cp16(sbB + (uint32_t)(r * RS + c) * 2u, W + (size_t)(n0 + r) * Hdim + c);
    }
    cp_commit();

    const int KT = Hdim / 32;  // 24
#pragma unroll 1
    for (int kt = 0; kt < KT; ++kt) {
        int cur = kt & 1;
        if (kt + 1 < KT) {
            int nxt = cur ^ 1;
#pragma unroll
            for (int i = 0; i < 2; i++) {
                int idx = tid + i * 256;
                int r = idx >> 2, c = (idx & 3) * 8;
                cp16(sbA + (uint32_t)(nxt * 128 * RS + r * RS + c) * 2u,
                     A + (size_t)(m0 + r) * Hdim + (kt + 1) * 32 + c);
                cp16(sbB + (uint32_t)(nxt * 128 * RS + r * RS + c) * 2u,
                     W + (size_t)(n0 + r) * Hdim + (kt + 1) * 32 + c);
            }
            cp_commit();
            cp_wait1();
        } else {
            cp_wait0();
        }
        __syncthreads();
        const uint32_t aBase = sbA + (uint32_t)(cur * 128 * RS) * 2u;
        const uint32_t bBase = sbB + (uint32_t)(cur * 128 * RS) * 2u;
#pragma unroll
        for (int kk = 0; kk < 2; ++kk) {
            uint32_t af[4][4], bf[4][2];
#pragma unroll
            for (int mt = 0; mt < 4; ++mt)
                ldsm_x4(af[mt][0], af[mt][1], af[mt][2], af[mt][3],
                        aBase + (uint32_t)(((wm * 64 + mt * 16 + a_row) * RS + kk * 16 + a_kh) * 2));
#pragma unroll
            for (int p = 0; p < 2; ++p)
                ldsm_x4(bf[2 * p][0], bf[2 * p][1], bf[2 * p + 1][0], bf[2 * p + 1][1],
                        bBase + (uint32_t)(((wn * 32 + p * 16 + b_row) * RS + kk * 16 + b_kh) * 2));
#pragma unroll
            for (int mt = 0; mt < 4; ++mt)
#pragma unroll
                for (int nt = 0; nt < 4; ++nt)
                    mma_f16(acc[mt][nt], af[mt], bf[nt]);
        }
        __syncthreads();
    }
#pragma unroll
    for (int mt = 0; mt < 4; ++mt) {
        int r = m0 + wm * 64 + mt * 16 + gid;
#pragma unroll
        for (int nt = 0; nt < 4; ++nt) {
            int c = n0 + wn * 32 + nt * 8 + tg * 2;
            *(__half2*)(&g_akh[(size_t)r * Hdim + c]) =
                __floats2half2_rn(acc[mt][nt][0], acc[mt][nt][1]);
            *(__half2*)(&g_akh[(size_t)(r + 8) * Hdim + c]) =
                __floats2half2_rn(acc[mt][nt][2], acc[mt][nt][3]);
        }
    }
}

// ---------------- Fused Kernel (compacted S, balanced tiles) ----------------
// Per CTA: 64 labels x batch b. 256 threads, warps 2x4.
// Phase 1: scores 64 x nv; warp wn owns INTERLEAVED 16-col tiles t = 4p + wn
//          (balances the nv-skip across warps). softmax -> probs in smem.
// Phase 2: out[64,768] = probs @ Xc, K-loop over ceil(nv/32), H split 2x384.
#define P_RS 520
#define F_ASTG (64 * RS)
#define F_BSTG (512 * RS)
#define F_B_OFF (3 * F_ASTG)
#define F_XT_OFF (64 * P_RS)
#define F_XTSTG (384 * RS)
#define F_RED_BYTE (2 * (F_XT_OFF + 3 * F_XTSTG))
#define F_IDX_BYTE (F_RED_BYTE + 64 * 4 * 4)
#define F_SMEM_BYTES (F_IDX_BYTE + 512 * 4 + 16)

__global__ __launch_bounds__(256) void k_fused(const __half* __restrict__ E,
                                               const __half* __restrict__ XT,
                                               float* __restrict__ O) {
    extern __shared__ __align__(16) float smem[];
    uint32_t sb = (uint32_t)__cvta_generic_to_shared(smem);
    float* red = (float*)((char*)smem + F_RED_BYTE);
    int* sidx  = (int*)((char*)smem + F_IDX_BYTE);

    const int tid  = threadIdx.x;
    const int lane = tid & 31, wid = tid >> 5;
    const int wm = wid & 1, wn = wid >> 1;  // 2 x 4
    const int tg = lane & 3, gid = lane >> 2;
    const int b  = blockIdx.y;
    const int m0 = blockIdx.x * 64;
    const __half* Bt = g_akh + (size_t)b * Sdim * Hdim;
    const int nv = g_nv[b];

    const int a_row = lane & 15, a_kh = (lane >> 4) << 3;
    const int b_row = ((lane >> 4) << 3) + (lane & 7), b_kh = ((lane >> 3) & 1) << 3;

    // stage compaction index into smem
    sidx[tid]       = g_idx[b * Sdim + tid];
    sidx[tid + 256] = g_idx[b * Sdim + tid + 256];
    __syncthreads();

    const uint32_t sbA = sb;
    const uint32_t sbB = sb + (uint32_t)F_B_OFF * 2u;

    // ================= Phase 1: scores + softmax =================
    float acc[2][16][4];
#pragma unroll
    for (int i = 0; i < 2; i++)
#pragma unroll
        for (int j = 0; j < 16; j++)
#pragma unroll
            for (int r = 0; r < 4; r++) acc[i][j][r] = 0.f;

    auto fill1 = [&](int st, int kt) {
        {   // A: 64 x 32 halves = 256 cp16
            int r = tid >> 2, c = (tid & 3) * 8;
            cp16(sbA + (uint32_t)(st * F_ASTG + r * RS + c) * 2u,
                 E + (size_t)(m0 + r) * Hdim + kt * 32 + c);
        }
#pragma unroll
        for (int i = 0; i < 8; i++) {  // B: nv x 32 halves (gathered rows)
            int idx = tid + i * 256;
            int r = idx >> 2, c = (idx & 3) * 8;
            if (r < nv)
                cp16(sbB + (uint32_t)(st * F_BSTG + r * RS + c) * 2u,
                     Bt + (size_t)sidx[r] * Hdim + kt * 32 + c);
        }
        cp_commit();
    };

    const int KT = Hdim / 32;  // 24
    fill1(0, 0);
    fill1(1, 1);
    cp_wait1();
    __syncthreads();

#pragma unroll 1
    for (int kt = 0; kt < KT; ++kt) {
        int cur = kt % 3;
        const uint32_t aBase = sbA + (uint32_t)(cur * F_ASTG) * 2u;
        const uint32_t bBase = sbB + (uint32_t)(cur * F_BSTG) * 2u;
#pragma unroll
        for (int kk = 0; kk < 2; ++kk) {
            uint32_t af[2][4], bf[16][2];
#pragma unroll
            for (int mt = 0; mt < 2; ++mt)
                ldsm_x4(af[mt][0], af[mt][1], af[mt][2], af[mt][3],
                        aBase + (uint32_t)(((wm * 32 + mt * 16 + a_row) * RS + kk * 16 + a_kh) * 2));
#pragma unroll
            for (int p = 0; p < 8; ++p) {
                int c0 = (4 * p + wn) * 16;   // interleaved tile -> balanced skip
                if (c0 < nv) {
                    ldsm_x4(bf[2 * p][0], bf[2 * p][1], bf[2 * p + 1][0], bf[2 * p + 1][1],
                            bBase + (uint32_t)(((c0 + b_row) * RS + kk * 16 + b_kh) * 2));
#pragma unroll
                    for (int mt = 0; mt < 2; ++mt) {
                        mma_f16(acc[mt][2 * p],     af[mt], bf[2 * p]);
                        mma_f16(acc[mt][2 * p + 1], af[mt], bf[2 * p + 1]);
                    }
                }
            }
        }
        if (kt + 2 < KT) fill1((kt + 2) % 3, kt + 2);
        if (kt + 1 < KT) { if (kt + 2 < KT) cp_wait1(); else cp_wait0(); }
        __syncthreads();
    }

    // softmax over compacted columns (valid = col < nv)
    // col(nt) = (4*(nt>>1) + wn)*16 + (nt&1)*8 + tg*2
    float mx[4] = {-1e30f, -1e30f, -1e30f, -1e30f};
#pragma unroll
    for (int mt = 0; mt < 2; ++mt)
#pragma unroll
        for (int nt = 0; nt < 16; ++nt) {
            int col = (4 * (nt >> 1) + wn) * 16 + (nt & 1) * 8 + tg * 2;
            if (col >= nv)     { acc[mt][nt][0] = -1e30f; acc[mt][nt][2] = -1e30f; }
            if (col + 1 >= nv) { acc[mt][nt][1] = -1e30f; acc[mt][nt][3] = -1e30f; }
            mx[mt * 2]     = fmaxf(mx[mt * 2],     fmaxf(acc[mt][nt][0], acc[mt][nt][1]));
            mx[mt * 2 + 1] = fmaxf(mx[mt * 2 + 1], fmaxf(acc[mt][nt][2], acc[mt][nt][3]));
        }
#pragma unroll
    for (int j = 0; j < 4; ++j) {
        mx[j] = fmaxf(mx[j], __shfl_xor_sync(0xffffffffu, mx[j], 1));
        mx[j] = fmaxf(mx[j], __shfl_xor_sync(0xffffffffu, mx[j], 2));
    }
    if (tg == 0) {
#pragma unroll
        for (int j = 0; j < 4; ++j) {
            int rl = wm * 32 + (j >> 1) * 16 + (j & 1) * 8 + gid;
            red[rl * 4 + wn] = mx[j];
        }
    }
    __syncthreads();
    float gmx[4];
#pragma unroll
    for (int j = 0; j < 4; ++j) {
        int rl = wm * 32 + (j >> 1) * 16 + (j & 1) * 8 + gid;
        float m = -1e30f;
#pragma unroll
        for (int w = 0; w < 4; ++w) m = fmaxf(m, red[rl * 4 + w]);
        gmx[j] = m;
    }
    __syncthreads();

    float sme[4] = {0.f, 0.f, 0.f, 0.f};
#pragma unroll
    for (int mt = 0; mt < 2; ++mt)
#pragma unroll
        for (int nt = 0; nt < 16; ++nt) {
            float e0 = __expf(acc[mt][nt][0] - gmx[mt * 2]);
            float e1 = __expf(acc[mt][nt][1] - gmx[mt * 2]);
            float e2 = __expf(acc[mt][nt][2] - gmx[mt * 2 + 1]);
            float e3 = __expf(acc[mt][nt][3] - gmx[mt * 2 + 1]);
            acc[mt][nt][0] = e0; acc[mt][nt][1] = e1;
            acc[mt][nt][2] = e2; acc[mt][nt][3] = e3;
            sme[mt * 2]     += e0 + e1;
            sme[mt * 2 + 1] += e2 + e3;
        }
#pragma unroll
    for (int j = 0; j < 4; ++j) {
        sme[j] += __shfl_xor_sync(0xffffffffu, sme[j], 1);
        sme[j] += __shfl_xor_sync(0xffffffffu, sme[j], 2);
    }
    if (tg == 0) {
#pragma unroll
        for (int j = 0; j < 4; ++j) {
            int rl = wm * 32 + (j >> 1) * 16 + (j & 1) * 8 + gid;
            red[rl * 4 + wn] = sme[j];
        }
    }
    __syncthreads();
    float inv[4];
#pragma unroll
    for (int j = 0; j < 4; ++j) {
        int rl = wm * 32 + (j >> 1) * 16 + (j & 1) * 8 + gid;
        float s = 0.f;
#pragma unroll
        for (int w = 0; w < 4; ++w) s += red[rl * 4 + w];
        inv[j] = 1.f / s;
    }

    // probs -> smem fp16 (aliases dead phase-1 stages); masked cols are exactly 0
    __half* probs = (__half*)smem;
#pragma unroll
    for (int mt = 0; mt < 2; ++mt) {
        int r0 = wm * 32 + mt * 16 + gid;
        int r1 = r0 + 8;
#pragma unroll
        for (int nt = 0; nt < 16; ++nt) {
            int col = (4 * (nt >> 1) + wn) * 16 + (nt & 1) * 8 + tg * 2;
            *(__half2*)(&probs[r0 * P_RS + col]) =
                __floats2half2_rn(acc[mt][nt][0] * inv[mt * 2], acc[mt][nt][1] * inv[mt * 2]);
            *(__half2*)(&probs[r1 * P_RS + col]) =
                __floats2half2_rn(acc[mt][nt][2] * inv[mt * 2 + 1], acc[mt][nt][3] * inv[mt * 2 + 1]);
        }
    }
    __syncthreads();

    // ================= Phase 2: out = probs @ Xc (K = nv, compacted) ========
    const uint32_t pB   = sb;                               // probs base
    const uint32_t sbXT = sb + (uint32_t)F_XT_OFF * 2u;
    const int KT2 = (nv + 31) >> 5;                         // dynamic K chunks

#pragma unroll 1
    for (int ht = 0; ht < 2; ++ht) {
        const __half* Xg = XT + ((size_t)b * Hdim + ht * 384) * Sdim;

        float acc2[2][12][4];
#pragma unroll
        for (int i = 0; i < 2; i++)
#pragma unroll
            for (int j = 0; j < 12; j++)
#pragma unroll
                for (int r = 0; r < 4; r++) acc2[i][j][r] = 0.f;

        auto fill2 = [&](int st, int kt) {
#pragma unroll
            for (int i = 0; i < 6; i++) {  // 384 x 32 halves = 1536 cp16
                int idx = tid + i * 256;
                int r = idx >> 2, c = (idx & 3) * 8;
                cp16(sbXT + (uint32_t)(st * F_XTSTG + r * RS + c) * 2u,
                     Xg + (size_t)r * Sdim + kt * 32 + c);
            }
            cp_commit();
        };

        fill2(0, 0);
        fill2(1, 1);
        cp_wait1();
        __syncthreads();

#pragma unroll 1
        for (int kt = 0; kt < KT2; ++kt) {
            int cur = kt % 3;
            const uint32_t xBase = sbXT + (uint32_t)(cur * F_XTSTG) * 2u;
#pragma unroll
            for (int kk = 0; kk < 2; ++kk) {
                uint32_t af[2][4], bf[12][2];
#pragma unroll
                for (int mt = 0; mt < 2; ++mt)
                    ldsm_x4(af[mt][0], af[mt][1], af[mt][2], af[mt][3],
                            pB + (uint32_t)(((wm * 32 + mt * 16 + a_row) * P_RS +
                                             kt * 32 + kk * 16 + a_kh) * 2));
#pragma unroll
                for (int p = 0; p < 6; ++p)
                    ldsm_x4(bf[2 * p][0], bf[2 * p][1], bf[2 * p + 1][0], bf[2 * p + 1][1],
                            xBase + (uint32_t)(((wn * 96 + p * 16 + b_row) * RS + kk * 16 + b_kh) * 2));
#pragma unroll
                for (int mt = 0; mt < 2; ++mt)
#pragma unroll
                    for (int nt = 0; nt < 12; ++nt)
                        mma_f16(acc2[mt][nt], af[mt], bf[nt]);
            }
            if (kt + 2 < KT2) fill2((kt + 2) % 3, kt + 2);
            if (kt + 1 < KT2) { if (kt + 2 < KT2) cp_wait1(); else cp_wait0(); }
            __syncthreads();
        }

        // epilogue: write this H-half
#pragma unroll
        for (int mt = 0; mt < 2; ++mt) {
            int r = m0 + wm * 32 + mt * 16 + gid;
            size_t base0 = ((size_t)b * Ldim + r) * Hdim;
            size_t base1 = ((size_t)b * Ldim + r + 8) * Hdim;
#pragma unroll
            for (int nt = 0; nt < 12; ++nt) {
                int c = ht * 384 + wn * 96 + nt * 8 + tg * 2;
                *(float2*)(&O[base0 + c]) = make_float2(acc2[mt][nt][0], acc2[mt][nt][1]);
                *(float2*)(&O[base1 + c]) = make_float2(acc2[mt][nt][2], acc2[mt][nt][3]);
            }
        }
    }
}

// ---------------- launcher ----------------
#define K1_SMEM_BYTES (4 * 128 * RS * 2)

extern "C" void kernel_launch(void* const* d_in, const int* in_sizes, int n_in,
                              void* d_out, int out_size) {
    const float* inputs = (const float*)d_in[0];
    const void*  masks  = d_in[1];
    const float* emb    = (const float*)d_in[2];
    const float* wkey   = (const float*)d_in[3];
    float* out = (float*)d_out;
    (void)in_sizes; (void)n_in; (void)out_size;

    cudaFuncSetAttribute(k_keyproj, cudaFuncAttributeMaxDynamicSharedMemorySize, K1_SMEM_BYTES);
    cudaFuncSetAttribute(k_fused,   cudaFuncAttributeMaxDynamicSharedMemorySize, F_SMEM_BYTES);

    __half* d_xh;  cudaGetSymbolAddress((void**)&d_xh,  g_xh);
    __half* d_xth; cudaGetSymbolAddress((void**)&d_xth, g_xth);
    __half* d_eh;  cudaGetSymbolAddress((void**)&d_eh,  g_eh);
    __half* d_wh;  cudaGetSymbolAddress((void**)&d_wh,  g_wh);

    k_detect<<<1, 256>>>((const int*)masks);
    k_scan<<<Bdim, 512>>>(masks);
    k_cvt<<<512, 256>>>((const float4*)inputs, (uint4*)d_xh, Bdim * Sdim * Hdim / 8);
    k_cvt<<<512, 256>>>((const float4*)emb,    (uint4*)d_eh, Ldim * Hdim / 8);
    k_cvt<<<256, 256>>>((const float4*)wkey,   (uint4*)d_wh, Hdim * Hdim / 8);
    k_gtr<<<dim3(Hdim / 32, Sdim / 32, Bdim), dim3(32, 8)>>>(inputs, d_xth);
    k_keyproj<<<dim3(6, 32, 1), 256, K1_SMEM_BYTES>>>(d_xh, d_wh);
    k_fused<<<dim3(Ldim / 64, Bdim), 256, F_SMEM_BYTES>>>(d_eh, d_xth, out);
}

// round 13
// speedup vs baseline: 1.2052x; 1.0424x over previous
#include <cuda_runtime.h>
#include <cuda_fp16.h>
#include <cstdint>

#define Bdim 8
#define Sdim 512
#define Hdim 768
#define Ldim 8192

// scratch (static device globals: allocation-free)
__device__ __half g_xhc[Bdim * Sdim * Hdim];                // gathered-compacted inputs fp16 [B,j,H]
__device__ __half g_xth[Bdim * Hdim * Sdim];                // gathered-compacted inputs^T [B,H,j] fp16
__device__ __half g_eh[Ldim * Hdim];                        // label_embedding fp16
__device__ __half g_wh[Hdim * Hdim];                        // W_key fp16
__device__ __half g_akh[Bdim * Sdim * Hdim];                // attn_key fp16 (compacted rows)
__device__ int    g_idx[Bdim * Sdim];                       // compaction index per batch
__device__ int    g_nv[Bdim];                               // valid count per batch

// ---------------- PTX helpers ----------------
__device__ __forceinline__ void mma_f16(float* c, const uint32_t* a, const uint32_t* b) {
    asm volatile(
        "mma.sync.aligned.m16n8k16.row.col.f32.f16.f16.f32 "
        "{%0,%1,%2,%3}, {%4,%5,%6,%7}, {%8,%9}, {%0,%1,%2,%3};\n"
        : "+f"(c[0]), "+f"(c[1]), "+f"(c[2]), "+f"(c[3])
        : "r"(a[0]), "r"(a[1]), "r"(a[2]), "r"(a[3]), "r"(b[0]), "r"(b[1]));
}

__device__ __forceinline__ void ldsm_x4(uint32_t& r0, uint32_t& r1, uint32_t& r2,
                                        uint32_t& r3, uint32_t addr) {
    asm volatile("ldmatrix.sync.aligned.m8n8.x4.shared.b16 {%0,%1,%2,%3}, [%4];"
                 : "=r"(r0), "=r"(r1), "=r"(r2), "=r"(r3) : "r"(addr));
}

__device__ __forceinline__ void cp16(uint32_t s, const void* g) {
    asm volatile("cp.async.cg.shared.global [%0], [%1], 16;\n" :: "r"(s), "l"(g));
}
__device__ __forceinline__ void cp_commit() { asm volatile("cp.async.commit_group;\n"); }
__device__ __forceinline__ void cp_wait1()  { asm volatile("cp.async.wait_group 1;\n"); }
__device__ __forceinline__ void cp_wait0()  { asm volatile("cp.async.wait_group 0;\n"); }

// ---------------- mask scan (with inline dtype detection) ----------------
// bool masks may arrive as uint8 (numpy bool) or int32. First 1024 int32 words
// (= 4096 B, safe under both layouts) all in {0,1} => int32 layout.
__global__ void k_scan(const void* __restrict__ masks) {
    __shared__ int sc[512];
    int b = blockIdx.x, t = threadIdx.x;
    const unsigned* mw = (const unsigned*)masks;
    int bad = (mw[t * 2] > 1u) || (mw[t * 2 + 1] > 1u);
    int is32 = __syncthreads_or(bad) ? 0 : 1;
    unsigned v = is32 ? (unsigned)((const int*)masks)[b * Sdim + t]
                      : (unsigned)((const unsigned char*)masks)[b * Sdim + t];
    int m = v ? 1 : 0;
    sc[t] = m;
    __syncthreads();
    for (int off = 1; off < 512; off <<= 1) {
        int x = (t >= off) ? sc[t - off] : 0;
        __syncthreads();
        sc[t] += x;
        __syncthreads();
    }
    int nv = sc[511];
    if (m) g_idx[b * Sdim + sc[t] - 1] = t;
    if (t >= nv) g_idx[b * Sdim + t] = 0;
    if (t == 0) g_nv[b] = nv;
}

// ---------------- prep: fp32 -> fp16 (two arrays, one launch) ----------------
__global__ void k_cvt2(const float4* __restrict__ s1, uint4* __restrict__ d1, int n1,
                       const float4* __restrict__ s2, uint4* __restrict__ d2, int n2) {
    int i = blockIdx.x * blockDim.x + threadIdx.x;
    int stride = gridDim.x * blockDim.x;
    for (; i < n1 + n2; i += stride) {
        const float4* src = (i < n1) ? s1 : s2;
        uint4* dst = (i < n1) ? d1 : d2;
        int j = (i < n1) ? i : i - n1;
        float4 a = src[2 * j], bq = src[2 * j + 1];
        __half2 h0 = __floats2half2_rn(a.x, a.y);
        __half2 h1 = __floats2half2_rn(a.z, a.w);
        __half2 h2 = __floats2half2_rn(bq.x, bq.y);
        __half2 h3 = __floats2half2_rn(bq.z, bq.w);
        uint4 o;
        o.x = *(uint32_t*)&h0; o.y = *(uint32_t*)&h1;
        o.z = *(uint32_t*)&h2; o.w = *(uint32_t*)&h3;
        dst[j] = o;
    }
}

// gather+convert: xhc[b][j][h] = half(X[b][idx[j]][h]);  xth[b][h][j] = same, transposed
__global__ void k_gtr(const float* __restrict__ X, __half* __restrict__ XT,
                      __half* __restrict__ XC) {
    __shared__ float t[32][33];
    int b = blockIdx.z;
    int j0 = blockIdx.y * 32, h0 = blockIdx.x * 32;
    int x = threadIdx.x, y = threadIdx.y;  // 32 x 8
    const float* srcb = X + (size_t)b * Sdim * Hdim;
#pragma unroll
    for (int i = 0; i < 32; i += 8) {
        int s = g_idx[b * Sdim + j0 + y + i];
        float v = srcb[(size_t)s * Hdim + h0 + x];
        t[y + i][x] = v;
        XC[((size_t)b * Sdim + j0 + y + i) * Hdim + h0 + x] = __float2half_rn(v);
    }
    __syncthreads();
    __half* dst = XT + ((size_t)b * Hdim + h0) * Sdim + j0;
#pragma unroll
    for (int i = 0; i < 32; i += 8)
        dst[(size_t)(y + i) * Sdim + x] = __float2half_rn(t[x][y + i]);
}

// Row stride in halves (80B): LDSM rows hit distinct 16B segs mod 128 -> conflict-free
#define RS 40

// ---------------- Kernel 1: attn_key(compacted) = xhc @ W_key^T ----------------
// BM=128 BN=128 BK=32, 256 threads (warps 2x4, WM=64 WN=32), 2-stage
// Early-exit for tiles entirely beyond nv[b].
__global__ __launch_bounds__(256) void k_keyproj(const __half* __restrict__ A,
                                                 const __half* __restrict__ W) {
    const int m0 = blockIdx.y * 128, n0 = blockIdx.x * 128;
    {   // compacted-row skip: rows m0..m0+127 are batch b = m0>>9, local j0 = m0&511
        int b = m0 >> 9, j0 = m0 & 511;
        if (j0 >= g_nv[b]) return;
    }
    extern __shared__ __align__(16) float smem[];
    uint32_t sb  = (uint32_t)__cvta_generic_to_shared(smem);
    const uint32_t sbA = sb;
    const uint32_t sbB = sb + 2u * 128u * RS * 2u;

    const int tid  = threadIdx.x;
    const int lane = tid & 31, wid = tid >> 5;
    const int wm = wid & 1, wn = wid >> 1;
    const int tg = lane & 3, gid = lane >> 2;

    const int a_row = lane & 15, a_kh = (lane >> 4) << 3;
    const int b_row = ((lane >> 4) << 3) + (lane & 7), b_kh = ((lane >> 3) & 1) << 3;

    float acc[4][4][4];
#pragma unroll
    for (int i = 0; i < 4; i++)
#pragma unroll
        for (int j = 0; j < 4; j++)
#pragma unroll
            for (int r = 0; r < 4; r++) acc[i][j][r] = 0.f;

#pragma unroll
    for (int i = 0; i < 2; i++) {
        int idx = tid + i * 256;
        int r = idx >> 2, c = (idx & 3) * 8;
        cp16(sbA + (uint32_t)(r * RS + c) * 2u, A + (size_t)(m0 + r) * Hdim + c);
        cp16(sbB + (uint32_t)(r * RS + c) * 2u, W + (size_t)(n0 + r) * Hdim + c);
    }
    cp_commit();

    const int KT = Hdim / 32;  // 24
#pragma unroll 1
    for (int kt = 0; kt < KT; ++kt) {
        int cur = kt & 1;
        if (kt + 1 < KT) {
            int nxt = cur ^ 1;
#pragma unroll
            for (int i = 0; i < 2; i++) {
                int idx = tid + i * 256;
                int r = idx >> 2, c = (idx & 3) * 8;
                cp16(sbA + (uint32_t)(nxt * 128 * RS + r * RS + c) * 2u,
                     A + (size_t)(m0 + r) * Hdim + (kt + 1) * 32 + c);
                cp16(sbB + (uint32_t)(nxt * 128 * RS + r * RS + c) * 2u,
                     W + (size_t)(n0 + r) * Hdim + (kt + 1) * 32 + c);
            }
            cp_commit();
            cp_wait1();
        } else {
            cp_wait0();
        }
        __syncthreads();
        const uint32_t aBase = sbA + (uint32_t)(cur * 128 * RS) * 2u;
        const uint32_t bBase = sbB + (uint32_t)(cur * 128 * RS) * 2u;
#pragma unroll
        for (int kk = 0; kk < 2; ++kk) {
            uint32_t af[4][4], bf[4][2];
#pragma unroll
            for (int mt = 0; mt < 4; ++mt)
                ldsm_x4(af[mt][0], af[mt][1], af[mt][2], af[mt][3],
                        aBase + (uint32_t)(((wm * 64 + mt * 16 + a_row) * RS + kk * 16 + a_kh) * 2));
#pragma unroll
            for (int p = 0; p < 2; ++p)
                ldsm_x4(bf[2 * p][0], bf[2 * p][1], bf[2 * p + 1][0], bf[2 * p + 1][1],
                        bBase + (uint32_t)(((wn * 32 + p * 16 + b_row) * RS + kk * 16 + b_kh) * 2));
#pragma unroll
            for (int mt = 0; mt < 4; ++mt)
#pragma unroll
                for (int nt = 0; nt < 4; ++nt)
                    mma_f16(acc[mt][nt], af[mt], bf[nt]);
        }
        __syncthreads();
    }
#pragma unroll
    for (int mt = 0; mt < 4; ++mt) {
        int r = m0 + wm * 64 + mt * 16 + gid;
#pragma unroll
        for (int nt = 0; nt < 4; ++nt) {
            int c = n0 + wn * 32 + nt * 8 + tg * 2;
            *(__half2*)(&g_akh[(size_t)r * Hdim + c]) =
                __floats2half2_rn(acc[mt][nt][0], acc[mt][nt][1]);
            *(__half2*)(&g_akh[(size_t)(r + 8) * Hdim + c]) =
                __floats2half2_rn(acc[mt][nt][2], acc[mt][nt][3]);
        }
    }
}

// ---------------- Fused Kernel (compacted S, balanced tiles) ----------------
// Per CTA: 64 labels x batch b. 256 threads, warps 2x4.
// Phase 1: scores 64 x nv (contiguous compacted attn_key rows); warp wn owns
//          interleaved 16-col tiles t = 4p + wn. softmax -> probs in smem.
// Phase 2: out[64,768] = probs @ Xc, K-loop over ceil(nv/32), H split 2x384.
#define P_RS 520
#define F_ASTG (64 * RS)
#define F_BSTG (512 * RS)
#define F_B_OFF (3 * F_ASTG)
#define F_XT_OFF (64 * P_RS)
#define F_XTSTG (384 * RS)
#define F_RED_BYTE (2 * (F_XT_OFF + 3 * F_XTSTG))
#define F_SMEM_BYTES (F_RED_BYTE + 64 * 4 * 4 + 16)

__global__ __launch_bounds__(256) void k_fused(const __half* __restrict__ E,
                                               const __half* __restrict__ XT,
                                               float* __restrict__ O) {
    extern __shared__ __align__(16) float smem[];
    uint32_t sb = (uint32_t)__cvta_generic_to_shared(smem);
    float* red = (float*)((char*)smem + F_RED_BYTE);

    const int tid  = threadIdx.x;
    const int lane = tid & 31, wid = tid >> 5;
    const int wm = wid & 1, wn = wid >> 1;  // 2 x 4
    const int tg = lane & 3, gid = lane >> 2;
    const int b  = blockIdx.y;
    const int m0 = blockIdx.x * 64;
    const __half* Bt = g_akh + (size_t)b * Sdim * Hdim;   // compacted rows
    const int nv = g_nv[b];

    const int a_row = lane & 15, a_kh = (lane >> 4) << 3;
    const int b_row = ((lane >> 4) << 3) + (lane & 7), b_kh = ((lane >> 3) & 1) << 3;

    const uint32_t sbA = sb;
    const uint32_t sbB = sb + (uint32_t)F_B_OFF * 2u;

    // ================= Phase 1: scores + softmax =================
    float acc[2][16][4];
#pragma unroll
    for (int i = 0; i < 2; i++)
#pragma unroll
        for (int j = 0; j < 16; j++)
#pragma unroll
            for (int r = 0; r < 4; r++) acc[i][j][r] = 0.f;

    auto fill1 = [&](int st, int kt) {
        {   // A: 64 x 32 halves = 256 cp16
            int r = tid >> 2, c = (tid & 3) * 8;
            cp16(sbA + (uint32_t)(st * F_ASTG + r * RS + c) * 2u,
                 E + (size_t)(m0 + r) * Hdim + kt * 32 + c);
        }
#pragma unroll
        for (int i = 0; i < 8; i++) {  // B: nv x 32 halves (contiguous compacted)
            int idx = tid + i * 256;
            int r = idx >> 2, c = (idx & 3) * 8;
            if (r < nv)
                cp16(sbB + (uint32_t)(st * F_BSTG + r * RS + c) * 2u,
                     Bt + (size_t)r * Hdim + kt * 32 + c);
        }
        cp_commit();
    };

    const int KT = Hdim / 32;  // 24
    fill1(0, 0);
    fill1(1, 1);
    cp_wait1();
    __syncthreads();

#pragma unroll 1
    for (int kt = 0; kt < KT; ++kt) {
        int cur = kt % 3;
        const uint32_t aBase = sbA + (uint32_t)(cur * F_ASTG) * 2u;
        const uint32_t bBase = sbB + (uint32_t)(cur * F_BSTG) * 2u;
#pragma unroll
        for (int kk = 0; kk < 2; ++kk) {
            uint32_t af[2][4], bf[16][2];
#pragma unroll
            for (int mt = 0; mt < 2; ++mt)
                ldsm_x4(af[mt][0], af[mt][1], af[mt][2], af[mt][3],
                        aBase + (uint32_t)(((wm * 32 + mt * 16 + a_row) * RS + kk * 16 + a_kh) * 2));
#pragma unroll
            for (int p = 0; p < 8; ++p) {
                int c0 = (4 * p + wn) * 16;   // interleaved tile -> balanced skip
                if (c0 < nv) {
                    ldsm_x4(bf[2 * p][0], bf[2 * p][1], bf[2 * p + 1][0], bf[2 * p + 1][1],
                            bBase + (uint32_t)(((c0 + b_row) * RS + kk * 16 + b_kh) * 2));
#pragma unroll
                    for (int mt = 0; mt < 2; ++mt) {
                        mma_f16(acc[mt][2 * p],     af[mt], bf[2 * p]);
                        mma_f16(acc[mt][2 * p + 1], af[mt], bf[2 * p + 1]);
                    }
                }
            }
        }
        if (kt + 2 < KT) fill1((kt + 2) % 3, kt + 2);
        if (kt + 1 < KT) { if (kt + 2 < KT) cp_wait1(); else cp_wait0(); }
        __syncthreads();
    }

    // softmax over compacted columns (valid = col < nv)
    // col(nt) = (4*(nt>>1) + wn)*16 + (nt&1)*8 + tg*2
    float mx[4] = {-1e30f, -1e30f, -1e30f, -1e30f};
#pragma unroll
    for (int mt = 0; mt < 2; ++mt)
#pragma unroll
        for (int nt = 0; nt < 16; ++nt) {
            int col = (4 * (nt >> 1) + wn) * 16 + (nt & 1) * 8 + tg * 2;
            if (col >= nv)     { acc[mt][nt][0] = -1e30f; acc[mt][nt][2] = -1e30f; }
            if (col + 1 >= nv) { acc[mt][nt][1] = -1e30f; acc[mt][nt][3] = -1e30f; }
            mx[mt * 2]     = fmaxf(mx[mt * 2],     fmaxf(acc[mt][nt][0], acc[mt][nt][1]));
            mx[mt * 2 + 1] = fmaxf(mx[mt * 2 + 1], fmaxf(acc[mt][nt][2], acc[mt][nt][3]));
        }
#pragma unroll
    for (int j = 0; j < 4; ++j) {
        mx[j] = fmaxf(mx[j], __shfl_xor_sync(0xffffffffu, mx[j], 1));
        mx[j] = fmaxf(mx[j], __shfl_xor_sync(0xffffffffu, mx[j], 2));
    }
    if (tg == 0) {
#pragma unroll
        for (int j = 0; j < 4; ++j) {
            int rl = wm * 32 + (j >> 1) * 16 + (j & 1) * 8 + gid;
            red[rl * 4 + wn] = mx[j];
        }
    }
    __syncthreads();
    float gmx[4];
#pragma unroll
    for (int j = 0; j < 4; ++j) {
        int rl = wm * 32 + (j >> 1) * 16 + (j & 1) * 8 + gid;
        float m = -1e30f;
#pragma unroll
        for (int w = 0; w < 4; ++w) m = fmaxf(m, red[rl * 4 + w]);
        gmx[j] = m;
    }
    __syncthreads();

    float sme[4] = {0.f, 0.f, 0.f, 0.f};
#pragma unroll
    for (int mt = 0; mt < 2; ++mt)
#pragma unroll
        for (int nt = 0; nt < 16; ++nt) {
            float e0 = __expf(acc[mt][nt][0] - gmx[mt * 2]);
            float e1 = __expf(acc[mt][nt][1] - gmx[mt * 2]);
            float e2 = __expf(acc[mt][nt][2] - gmx[mt * 2 + 1]);
            float e3 = __expf(acc[mt][nt][3] - gmx[mt * 2 + 1]);
            acc[mt][nt][0] = e0; acc[mt][nt][1] = e1;
            acc[mt][nt][2] = e2; acc[mt][nt][3] = e3;
            sme[mt * 2]     += e0 + e1;
            sme[mt * 2 + 1] += e2 + e3;
        }
#pragma unroll
    for (int j = 0; j < 4; ++j) {
        sme[j] += __shfl_xor_sync(0xffffffffu, sme[j], 1);
        sme[j] += __shfl_xor_sync(0xffffffffu, sme[j], 2);
    }
    if (tg == 0) {
#pragma unroll
        for (int j = 0; j < 4; ++j) {
            int rl = wm * 32 + (j >> 1) * 16 + (j & 1) * 8 + gid;
            red[rl * 4 + wn] = sme[j];
        }
    }
    __syncthreads();
    float inv[4];
#pragma unroll
    for (int j = 0; j < 4; ++j) {
        int rl = wm * 32 + (j >> 1) * 16 + (j & 1) * 8 + gid;
        float s = 0.f;
#pragma unroll
        for (int w = 0; w < 4; ++w) s += red[rl * 4 + w];
        inv[j] = 1.f / s;
    }

    // probs -> smem fp16 (aliases dead phase-1 stages); masked cols are exactly 0
    __half* probs = (__half*)smem;
#pragma unroll
    for (int mt = 0; mt < 2; ++mt) {
        int r0 = wm * 32 + mt * 16 + gid;
        int r1 = r0 + 8;
#pragma unroll
        for (int nt = 0; nt < 16; ++nt) {
            int col = (4 * (nt >> 1) + wn) * 16 + (nt & 1) * 8 + tg * 2;
            *(__half2*)(&probs[r0 * P_RS + col]) =
                __floats2half2_rn(acc[mt][nt][0] * inv[mt * 2], acc[mt][nt][1] * inv[mt * 2]);
            *(__half2*)(&probs[r1 * P_RS + col]) =
                __floats2half2_rn(acc[mt][nt][2] * inv[mt * 2 + 1], acc[mt][nt][3] * inv[mt * 2 + 1]);
        }
    }
    __syncthreads();

    // ================= Phase 2: out = probs @ Xc (K = nv, compacted) ========
    const uint32_t pB   = sb;                               // probs base
    const uint32_t sbXT = sb + (uint32_t)F_XT_OFF * 2u;
    const int KT2 = (nv + 31) >> 5;                         // dynamic K chunks

#pragma unroll 1
    for (int ht = 0; ht < 2; ++ht) {
        const __half* Xg = XT + ((size_t)b * Hdim + ht * 384) * Sdim;

        float acc2[2][12][4];
#pragma unroll
        for (int i = 0; i < 2; i++)
#pragma unroll
            for (int j = 0; j < 12; j++)
#pragma unroll
                for (int r = 0; r < 4; r++) acc2[i][j][r] = 0.f;

        auto fill2 = [&](int st, int kt) {
#pragma unroll
            for (int i = 0; i < 6; i++) {  // 384 x 32 halves = 1536 cp16
                int idx = tid + i * 256;
                int r = idx >> 2, c = (idx & 3) * 8;
                cp16(sbXT + (uint32_t)(st * F_XTSTG + r * RS + c) * 2u,
                     Xg + (size_t)r * Sdim + kt * 32 + c);
            }
            cp_commit();
        };

        fill2(0, 0);
        fill2(1, 1);
        cp_wait1();
        __syncthreads();

#pragma unroll 1
        for (int kt = 0; kt < KT2; ++kt) {
            int cur = kt % 3;
            const uint32_t xBase = sbXT + (uint32_t)(cur * F_XTSTG) * 2u;
#pragma unroll
            for (int kk = 0; kk < 2; ++kk) {
                uint32_t af[2][4], bf[12][2];
#pragma unroll
                for (int mt = 0; mt < 2; ++mt)
                    ldsm_x4(af[mt][0], af[mt][1], af[mt][2], af[mt][3],
                            pB + (uint32_t)(((wm * 32 + mt * 16 + a_row) * P_RS +
                                             kt * 32 + kk * 16 + a_kh) * 2));
#pragma unroll
                for (int p = 0; p < 6; ++p)
                    ldsm_x4(bf[2 * p][0], bf[2 * p][1], bf[2 * p + 1][0], bf[2 * p + 1][1],
                            xBase + (uint32_t)(((wn * 96 + p * 16 + b_row) * RS + kk * 16 + b_kh) * 2));
#pragma unroll
                for (int mt = 0; mt < 2; ++mt)
#pragma unroll
                    for (int nt = 0; nt < 12; ++nt)
                        mma_f16(acc2[mt][nt], af[mt], bf[nt]);
            }
            if (kt + 2 < KT2) fill2((kt + 2) % 3, kt + 2);
            if (kt + 1 < KT2) { if (kt + 2 < KT2) cp_wait1(); else cp_wait0(); }
            __syncthreads();
        }

        // epilogue: write this H-half
#pragma unroll
        for (int mt = 0; mt < 2; ++mt) {
            int r = m0 + wm * 32 + mt * 16 + gid;
            size_t base0 = ((size_t)b * Ldim + r) * Hdim;
            size_t base1 = ((size_t)b * Ldim + r + 8) * Hdim;
#pragma unroll
            for (int nt = 0; nt < 12; ++nt) {
                int c = ht * 384 + wn * 96 + nt * 8 + tg * 2;
                *(float2*)(&O[base0 + c]) = make_float2(acc2[mt][nt][0], acc2[mt][nt][1]);
                *(float2*)(&O[base1 + c]) = make_float2(acc2[mt][nt][2], acc2[mt][nt][3]);
            }
        }
    }
}

// ---------------- launcher ----------------
#define K1_SMEM_BYTES (4 * 128 * RS * 2)

extern "C" void kernel_launch(void* const* d_in, const int* in_sizes, int n_in,
                              void* d_out, int out_size) {
    const float* inputs = (const float*)d_in[0];
    const void*  masks  = d_in[1];
    const float* emb    = (const float*)d_in[2];
    const float* wkey   = (const float*)d_in[3];
    float* out = (float*)d_out;
    (void)in_sizes; (void)n_in; (void)out_size;

    cudaFuncSetAttribute(k_keyproj, cudaFuncAttributeMaxDynamicSharedMemorySize, K1_SMEM_BYTES);
    cudaFuncSetAttribute(k_fused,   cudaFuncAttributeMaxDynamicSharedMemorySize, F_SMEM_BYTES);

    __half* d_xhc; cudaGetSymbolAddress((void**)&d_xhc, g_xhc);
    __half* d_xth; cudaGetSymbolAddress((void**)&d_xth, g_xth);
    __half* d_eh;  cudaGetSymbolAddress((void**)&d_eh,  g_eh);
    __half* d_wh;  cudaGetSymbolAddress((void**)&d_wh,  g_wh);

    k_scan<<<Bdim, 512>>>(masks);
    k_cvt2<<<512, 256>>>((const float4*)emb,  (uint4*)d_eh, Ldim * Hdim / 8,
                         (const float4*)wkey, (uint4*)d_wh, Hdim * Hdim / 8);
    k_gtr<<<dim3(Hdim / 32, Sdim / 32, Bdim), dim3(32, 8)>>>(inputs, d_xth, d_xhc);
    k_keyproj<<<dim3(6, 32, 1), 256, K1_SMEM_BYTES>>>(d_xhc, d_wh);
    k_fused<<<dim3(Ldim / 64, Bdim), 256, F_SMEM_BYTES>>>(d_eh, d_xth, out);
}

// round 14
// speedup vs baseline: 1.3250x; 1.0994x over previous
#include <cuda_runtime.h>
#include <cuda_fp16.h>
#include <cstdint>

#define Bdim 8
#define Sdim 512
#define Hdim 768
#define Ldim 8192

// scratch (static device globals: allocation-free)
__device__ __half g_xhc[Bdim * Sdim * Hdim];                // gathered-compacted inputs fp16 [B,j,H]
__device__ __half g_xth[Bdim * Hdim * Sdim];                // gathered-compacted inputs^T [B,H,j] fp16
__device__ __half g_eh[Ldim * Hdim];                        // label_embedding fp16
__device__ __half g_wh[Hdim * Hdim];                        // W_key fp16
__device__ __half g_akh[Bdim * Sdim * Hdim];                // attn_key fp16 (compacted rows)
__device__ int    g_idx[Bdim * Sdim];                       // compaction index per batch
__device__ int    g_nv[Bdim];                               // valid count per batch

// ---------------- PTX helpers ----------------
__device__ __forceinline__ void mma_f16(float* c, const uint32_t* a, const uint32_t* b) {
    asm volatile(
        "mma.sync.aligned.m16n8k16.row.col.f32.f16.f16.f32 "
        "{%0,%1,%2,%3}, {%4,%5,%6,%7}, {%8,%9}, {%0,%1,%2,%3};\n"
        : "+f"(c[0]), "+f"(c[1]), "+f"(c[2]), "+f"(c[3])
        : "r"(a[0]), "r"(a[1]), "r"(a[2]), "r"(a[3]), "r"(b[0]), "r"(b[1]));
}

__device__ __forceinline__ void ldsm_x4(uint32_t& r0, uint32_t& r1, uint32_t& r2,
                                        uint32_t& r3, uint32_t addr) {
    asm volatile("ldmatrix.sync.aligned.m8n8.x4.shared.b16 {%0,%1,%2,%3}, [%4];"
                 : "=r"(r0), "=r"(r1), "=r"(r2), "=r"(r3) : "r"(addr));
}

__device__ __forceinline__ void cp16(uint32_t s, const void* g) {
    asm volatile("cp.async.cg.shared.global [%0], [%1], 16;\n" :: "r"(s), "l"(g));
}
__device__ __forceinline__ void cp_commit() { asm volatile("cp.async.commit_group;\n"); }
__device__ __forceinline__ void cp_wait1()  { asm volatile("cp.async.wait_group 1;\n"); }
__device__ __forceinline__ void cp_wait0()  { asm volatile("cp.async.wait_group 0;\n"); }

// ---------------- mask scan (with inline dtype detection) ----------------
__global__ void k_scan(const void* __restrict__ masks) {
    __shared__ int sc[512];
    int b = blockIdx.x, t = threadIdx.x;
    const unsigned* mw = (const unsigned*)masks;
    int bad = (mw[t * 2] > 1u) || (mw[t * 2 + 1] > 1u);
    int is32 = __syncthreads_or(bad) ? 0 : 1;
    unsigned v = is32 ? (unsigned)((const int*)masks)[b * Sdim + t]
                      : (unsigned)((const unsigned char*)masks)[b * Sdim + t];
    int m = v ? 1 : 0;
    sc[t] = m;
    __syncthreads();
    for (int off = 1; off < 512; off <<= 1) {
        int x = (t >= off) ? sc[t - off] : 0;
        __syncthreads();
        sc[t] += x;
        __syncthreads();
    }
    int nv = sc[511];
    if (m) g_idx[b * Sdim + sc[t] - 1] = t;
    if (t >= nv) g_idx[b * Sdim + t] = 0;
    if (t == 0) g_nv[b] = nv;
}

// ---------------- prep: fp32 -> fp16 (two arrays, one launch) ----------------
__global__ void k_cvt2(const float4* __restrict__ s1, uint4* __restrict__ d1, int n1,
                       const float4* __restrict__ s2, uint4* __restrict__ d2, int n2) {
    int i = blockIdx.x * blockDim.x + threadIdx.x;
    int stride = gridDim.x * blockDim.x;
    for (; i < n1 + n2; i += stride) {
        const float4* src = (i < n1) ? s1 : s2;
        uint4* dst = (i < n1) ? d1 : d2;
        int j = (i < n1) ? i : i - n1;
        float4 a = src[2 * j], bq = src[2 * j + 1];
        __half2 h0 = __floats2half2_rn(a.x, a.y);
        __half2 h1 = __floats2half2_rn(a.z, a.w);
        __half2 h2 = __floats2half2_rn(bq.x, bq.y);
        __half2 h3 = __floats2half2_rn(bq.z, bq.w);
        uint4 o;
        o.x = *(uint32_t*)&h0; o.y = *(uint32_t*)&h1;
        o.z = *(uint32_t*)&h2; o.w = *(uint32_t*)&h3;
        dst[j] = o;
    }
}

// gather+convert: xhc[b][j][h] = half(X[b][idx[j]][h]);  xth[b][h][j] = transposed
__global__ void k_gtr(const float* __restrict__ X, __half* __restrict__ XT,
                      __half* __restrict__ XC) {
    __shared__ float t[32][33];
    int b = blockIdx.z;
    int j0 = blockIdx.y * 32, h0 = blockIdx.x * 32;
    int x = threadIdx.x, y = threadIdx.y;  // 32 x 8
    const float* srcb = X + (size_t)b * Sdim * Hdim;
#pragma unroll
    for (int i = 0; i < 32; i += 8) {
        int s = g_idx[b * Sdim + j0 + y + i];
        float v = srcb[(size_t)s * Hdim + h0 + x];
        t[y + i][x] = v;
        XC[((size_t)b * Sdim + j0 + y + i) * Hdim + h0 + x] = __float2half_rn(v);
    }
    __syncthreads();
    __half* dst = XT + ((size_t)b * Hdim + h0) * Sdim + j0;
#pragma unroll
    for (int i = 0; i < 32; i += 8)
        dst[(size_t)(y + i) * Sdim + x] = __float2half_rn(t[x][y + i]);
}

#define RS1 40   // keyproj row stride (halves)
#define RS  72   // fused BK=64 row stride (halves); 9 == 1 mod 8 -> LDSM conflict-free

// ---------------- Kernel 1: attn_key(compacted) = xhc @ W_key^T ----------------
__global__ __launch_bounds__(256) void k_keyproj(const __half* __restrict__ A,
                                                 const __half* __restrict__ W) {
    const int m0 = blockIdx.y * 128, n0 = blockIdx.x * 128;
    {
        int b = m0 >> 9, j0 = m0 & 511;
        if (j0 >= g_nv[b]) return;
    }
    extern __shared__ __align__(16) float smem[];
    uint32_t sb  = (uint32_t)__cvta_generic_to_shared(smem);
    const uint32_t sbA = sb;
    const uint32_t sbB = sb + 2u * 128u * RS1 * 2u;

    const int tid  = threadIdx.x;
    const int lane = tid & 31, wid = tid >> 5;
    const int wm = wid & 1, wn = wid >> 1;
    const int tg = lane & 3, gid = lane >> 2;

    const int a_row = lane & 15, a_kh = (lane >> 4) << 3;
    const int b_row = ((lane >> 4) << 3) + (lane & 7), b_kh = ((lane >> 3) & 1) << 3;

    float acc[4][4][4];
#pragma unroll
    for (int i = 0; i < 4; i++)
#pragma unroll
        for (int j = 0; j < 4; j++)
#pragma unroll
            for (int r = 0; r < 4; r++) acc[i][j][r] = 0.f;

#pragma unroll
    for (int i = 0; i < 2; i++) {
        int idx = tid + i * 256;
        int r = idx >> 2, c = (idx & 3) * 8;
        cp16(sbA + (uint32_t)(r * RS1 + c) * 2u, A + (size_t)(m0 + r) * Hdim + c);
        cp16(sbB + (uint32_t)(r * RS1 + c) * 2u, W + (size_t)(n0 + r) * Hdim + c);
    }
    cp_commit();

    const int KT = Hdim / 32;  // 24
#pragma unroll 1
    for (int kt = 0; kt < KT; ++kt) {
        int cur = kt & 1;
        if (kt + 1 < KT) {
            int nxt = cur ^ 1;
#pragma unroll
            for (int i = 0; i < 2; i++) {
                int idx = tid + i * 256;
                int r = idx >> 2, c = (idx & 3) * 8;
                cp16(sbA + (uint32_t)(nxt * 128 * RS1 + r * RS1 + c) * 2u,
                     A + (size_t)(m0 + r) * Hdim + (kt + 1) * 32 + c);
                cp16(sbB + (uint32_t)(nxt * 128 * RS1 + r * RS1 + c) * 2u,
                     W + (size_t)(n0 + r) * Hdim + (kt + 1) * 32 + c);
            }
            cp_commit();
            cp_wait1();
        } else {
            cp_wait0();
        }
        __syncthreads();
        const uint32_t aBase = sbA + (uint32_t)(cur * 128 * RS1) * 2u;
        const uint32_t bBase = sbB + (uint32_t)(cur * 128 * RS1) * 2u;
#pragma unroll
        for (int kk = 0; kk < 2; ++kk) {
            uint32_t af[4][4], bf[4][2];
#pragma unroll
            for (int mt = 0; mt < 4; ++mt)
                ldsm_x4(af[mt][0], af[mt][1], af[mt][2], af[mt][3],
                        aBase + (uint32_t)(((wm * 64 + mt * 16 + a_row) * RS1 + kk * 16 + a_kh) * 2));
#pragma unroll
            for (int p = 0; p < 2; ++p)
                ldsm_x4(bf[2 * p][0], bf[2 * p][1], bf[2 * p + 1][0], bf[2 * p + 1][1],
                        bBase + (uint32_t)(((wn * 32 + p * 16 + b_row) * RS1 + kk * 16 + b_kh) * 2));
#pragma unroll
            for (int mt = 0; mt < 4; ++mt)
#pragma unroll
                for (int nt = 0; nt < 4; ++nt)
                    mma_f16(acc[mt][nt], af[mt], bf[nt]);
        }
        __syncthreads();
    }
#pragma unroll
    for (int mt = 0; mt < 4; ++mt) {
        int r = m0 + wm * 64 + mt * 16 + gid;
#pragma unroll
        for (int nt = 0; nt < 4; ++nt) {
            int c = n0 + wn * 32 + nt * 8 + tg * 2;
            *(__half2*)(&g_akh[(size_t)r * Hdim + c]) =
                __floats2half2_rn(acc[mt][nt][0], acc[mt][nt][1]);
            *(__half2*)(&g_akh[(size_t)(r + 8) * Hdim + c]) =
                __floats2half2_rn(acc[mt][nt][2], acc[mt][nt][3]);
        }
    }
}

// ---------------- Fused Kernel (compacted S, 512 threads, BK=64) -----------
// Phase 1: scores 64 x nv; warps 2x8; warp wn owns interleaved tiles t = 8p+wn.
// Phase 2: out[64,768] = probs @ Xc; 2 H-halves of 384; warps 2x8 (WN=48).
#define P_RS 520
#define F_ASTG (64 * RS)
#define F_BSTG (512 * RS)
#define F_B_OFF (2 * F_ASTG)
#define F_XT_OFF (64 * P_RS)
#define F_XTSTG (384 * RS)
#define F_RED_BYTE (2 * (F_XT_OFF + 2 * F_XTSTG))
#define F_SMEM_BYTES (F_RED_BYTE + 64 * 8 * 4 + 16)

__global__ __launch_bounds__(512) void k_fused(const __half* __restrict__ E,
                                               const __half* __restrict__ XT,
                                               float* __restrict__ O) {
    extern __shared__ __align__(16) float smem[];
    uint32_t sb = (uint32_t)__cvta_generic_to_shared(smem);
    float* red = (float*)((char*)smem + F_RED_BYTE);

    const int tid  = threadIdx.x;
    const int lane = tid & 31, wid = tid >> 5;
    const int wm = wid & 1, wn = wid >> 1;  // 2 x 8
    const int tg = lane & 3, gid = lane >> 2;
    const int b  = blockIdx.y;
    const int m0 = blockIdx.x * 64;
    const __half* Bt = g_akh + (size_t)b * Sdim * Hdim;   // compacted rows
    const int nv = g_nv[b];

    const int a_row = lane & 15, a_kh = (lane >> 4) << 3;
    const int b_row = ((lane >> 4) << 3) + (lane & 7), b_kh = ((lane >> 3) & 1) << 3;

    const uint32_t sbA = sb;
    const uint32_t sbB = sb + (uint32_t)F_B_OFF * 2u;

    // ================= Phase 1: scores + softmax =================
    float acc[2][8][4];
#pragma unroll
    for (int i = 0; i < 2; i++)
#pragma unroll
        for (int j = 0; j < 8; j++)
#pragma unroll
            for (int r = 0; r < 4; r++) acc[i][j][r] = 0.f;

    auto fill1 = [&](int st, int kt) {
        {   // A: 64 rows x 8 chunks = 512 cp16
            int r = tid >> 3, c = (tid & 7) * 8;
            cp16(sbA + (uint32_t)(st * F_ASTG + r * RS + c) * 2u,
                 E + (size_t)(m0 + r) * Hdim + kt * 64 + c);
        }
#pragma unroll
        for (int i = 0; i < 8; i++) {  // B: nv rows x 8 chunks
            int idx = tid + i * 512;
            int r = idx >> 3, c = (idx & 7) * 8;
            if (r < nv)
                cp16(sbB + (uint32_t)(st * F_BSTG + r * RS + c) * 2u,
                     Bt + (size_t)r * Hdim + kt * 64 + c);
        }
        cp_commit();
    };

    const int KT = Hdim / 64;  // 12
    fill1(0, 0);
    cp_commit();  // keep group accounting simple (empty group)
#pragma unroll 1
    for (int kt = 0; kt < KT; ++kt) {
        int cur = kt & 1;
        if (kt + 1 < KT) { fill1(cur ^ 1, kt + 1); cp_wait1(); }
        else             { cp_wait0(); }
        __syncthreads();
        const uint32_t aBase = sbA + (uint32_t)(cur * F_ASTG) * 2u;
        const uint32_t bBase = sbB + (uint32_t)(cur * F_BSTG) * 2u;
#pragma unroll
        for (int kk = 0; kk < 4; ++kk) {
            uint32_t af[2][4], bf[8][2];
#pragma unroll
            for (int mt = 0; mt < 2; ++mt)
                ldsm_x4(af[mt][0], af[mt][1], af[mt][2], af[mt][3],
                        aBase + (uint32_t)(((wm * 32 + mt * 16 + a_row) * RS + kk * 16 + a_kh) * 2));
#pragma unroll
            for (int p = 0; p < 4; ++p) {
                int c0 = (8 * p + wn) * 16;   // interleaved tile -> balanced skip
                if (c0 < nv) {
                    ldsm_x4(bf[2 * p][0], bf[2 * p][1], bf[2 * p + 1][0], bf[2 * p + 1][1],
                            bBase + (uint32_t)(((c0 + b_row) * RS + kk * 16 + b_kh) * 2));
#pragma unroll
                    for (int mt = 0; mt < 2; ++mt) {
                        mma_f16(acc[mt][2 * p],     af[mt], bf[2 * p]);
                        mma_f16(acc[mt][2 * p + 1], af[mt], bf[2 * p + 1]);
                    }
                }
            }
        }
        __syncthreads();
    }

    // softmax over compacted columns: col(nt) = (8*(nt>>1)+wn)*16 + (nt&1)*8 + tg*2
    float mx[4] = {-1e30f, -1e30f, -1e30f, -1e30f};
#pragma unroll
    for (int mt = 0; mt < 2; ++mt)
#pragma unroll
        for (int nt = 0; nt < 8; ++nt) {
            int col = (8 * (nt >> 1) + wn) * 16 + (nt & 1) * 8 + tg * 2;
            if (col >= nv)     { acc[mt][nt][0] = -1e30f; acc[mt][nt][2] = -1e30f; }
            if (col + 1 >= nv) { acc[mt][nt][1] = -1e30f; acc[mt][nt][3] = -1e30f; }
            mx[mt * 2]     = fmaxf(mx[mt * 2],     fmaxf(acc[mt][nt][0], acc[mt][nt][1]));
            mx[mt * 2 + 1] = fmaxf(mx[mt * 2 + 1], fmaxf(acc[mt][nt][2], acc[mt][nt][3]));
        }
#pragma unroll
    for (int j = 0; j < 4; ++j) {
        mx[j] = fmaxf(mx[j], __shfl_xor_sync(0xffffffffu, mx[j], 1));
        mx[j] = fmaxf(mx[j], __shfl_xor_sync(0xffffffffu, mx[j], 2));
    }
    if (tg == 0) {
#pragma unroll
        for (int j = 0; j < 4; ++j) {
            int rl = wm * 32 + (j >> 1) * 16 + (j & 1) * 8 + gid;
            red[rl * 8 + wn] = mx[j];
        }
    }
    __syncthreads();
    float gmx[4];
#pragma unroll
    for (int j = 0; j < 4; ++j) {
        int rl = wm * 32 + (j >> 1) * 16 + (j & 1) * 8 + gid;
        float m = -1e30f;
#pragma unroll
        for (int w = 0; w < 8; ++w) m = fmaxf(m, red[rl * 8 + w]);
        gmx[j] = m;
    }
    __syncthreads();

    float sme[4] = {0.f, 0.f, 0.f, 0.f};
#pragma unroll
    for (int mt = 0; mt < 2; ++mt)
#pragma unroll
        for (int nt = 0; nt < 8; ++nt) {
            float e0 = __expf(acc[mt][nt][0] - gmx[mt * 2]);
            float e1 = __expf(acc[mt][nt][1] - gmx[mt * 2]);
            float e2 = __expf(acc[mt][nt][2] - gmx[mt * 2 + 1]);
            float e3 = __expf(acc[mt][nt][3] - gmx[mt * 2 + 1]);
            acc[mt][nt][0] = e0; acc[mt][nt][1] = e1;
            acc[mt][nt][2] = e2; acc[mt][nt][3] = e3;
            sme[mt * 2]     += e0 + e1;
            sme[mt * 2 + 1] += e2 + e3;
        }
#pragma unroll
    for (int j = 0; j < 4; ++j) {
        sme[j] += __shfl_xor_sync(0xffffffffu, sme[j], 1);
        sme[j] += __shfl_xor_sync(0xffffffffu, sme[j], 2);
    }
    if (tg == 0) {
#pragma unroll
        for (int j = 0; j < 4; ++j) {
            int rl = wm * 32 + (j >> 1) * 16 + (j & 1) * 8 + gid;
            red[rl * 8 + wn] = sme[j];
        }
    }
    __syncthreads();
    float inv[4];
#pragma unroll
    for (int j = 0; j < 4; ++j) {
        int rl = wm * 32 + (j >> 1) * 16 + (j & 1) * 8 + gid;
        float s = 0.f;
#pragma unroll
        for (int w = 0; w < 8; ++w) s += red[rl * 8 + w];
        inv[j] = 1.f / s;
    }

    // probs -> smem fp16 (aliases dead phase-1 stages); masked cols exactly 0
    __half* probs = (__half*)smem;
#pragma unroll
    for (int mt = 0; mt < 2; ++mt) {
        int r0 = wm * 32 + mt * 16 + gid;
        int r1 = r0 + 8;
#pragma unroll
        for (int nt = 0; nt < 8; ++nt) {
            int col = (8 * (nt >> 1) + wn) * 16 + (nt & 1) * 8 + tg * 2;
            *(__half2*)(&probs[r0 * P_RS + col]) =
                __floats2half2_rn(acc[mt][nt][0] * inv[mt * 2], acc[mt][nt][1] * inv[mt * 2]);
            *(__half2*)(&probs[r1 * P_RS + col]) =
                __floats2half2_rn(acc[mt][nt][2] * inv[mt * 2 + 1], acc[mt][nt][3] * inv[mt * 2 + 1]);
        }
    }
    __syncthreads();

    // ================= Phase 2: out = probs @ Xc (K = nv, BK=64) ============
    const uint32_t pB   = sb;
    const uint32_t sbXT = sb + (uint32_t)F_XT_OFF * 2u;
    const int KT2 = (nv + 63) >> 6;   // <= 8

#pragma unroll 1
    for (int ht = 0; ht < 2; ++ht) {
        const __half* Xg = XT + ((size_t)b * Hdim + ht * 384) * Sdim;

        float acc2[2][6][4];
#pragma unroll
        for (int i = 0; i < 2; i++)
#pragma unroll
            for (int j = 0; j < 6; j++)
#pragma unroll
                for (int r = 0; r < 4; r++) acc2[i][j][r] = 0.f;

        auto fill2 = [&](int st, int kt) {
#pragma unroll
            for (int i = 0; i < 6; i++) {  // 384 rows x 8 chunks = 3072 cp16
                int idx = tid + i * 512;
                int r = idx >> 3, c = (idx & 7) * 8;
                cp16(sbXT + (uint32_t)(st * F_XTSTG + r * RS + c) * 2u,
                     Xg + (size_t)r * Sdim + kt * 64 + c);
            }
            cp_commit();
        };

        fill2(0, 0);
#pragma unroll 1
        for (int kt = 0; kt < KT2; ++kt) {
            int cur = kt & 1;
            if (kt + 1 < KT2) { fill2(cur ^ 1, kt + 1); cp_wait1(); }
            else              { cp_wait0(); }
            __syncthreads();
            const uint32_t xBase = sbXT + (uint32_t)(cur * F_XTSTG) * 2u;
#pragma unroll
            for (int kk = 0; kk < 4; ++kk) {
                uint32_t af[2][4], bf[6][2];
#pragma unroll
                for (int mt = 0; mt < 2; ++mt)
                    ldsm_x4(af[mt][0], af[mt][1], af[mt][2], af[mt][3],
                            pB + (uint32_t)(((wm * 32 + mt * 16 + a_row) * P_RS +
                                             kt * 64 + kk * 16 + a_kh) * 2));
#pragma unroll
                for (int p = 0; p < 3; ++p)
                    ldsm_x4(bf[2 * p][0], bf[2 * p][1], bf[2 * p + 1][0], bf[2 * p + 1][1],
                            xBase + (uint32_t)(((wn * 48 + p * 16 + b_row) * RS + kk * 16 + b_kh) * 2));
#pragma unroll
                for (int mt = 0; mt < 2; ++mt)
#pragma unroll
                    for (int nt = 0; nt < 6; ++nt)
                        mma_f16(acc2[mt][nt], af[mt], bf[nt]);
            }
            __syncthreads();
        }

        // epilogue: write this H-half
#pragma unroll
        for (int mt = 0; mt < 2; ++mt) {
            int r = m0 + wm * 32 + mt * 16 + gid;
            size_t base0 = ((size_t)b * Ldim + r) * Hdim;
            size_t base1 = ((size_t)b * Ldim + r + 8) * Hdim;
#pragma unroll
            for (int nt = 0; nt < 6; ++nt) {
                int c = ht * 384 + wn * 48 + nt * 8 + tg * 2;
                *(float2*)(&O[base0 + c]) = make_float2(acc2[mt][nt][0], acc2[mt][nt][1]);
                *(float2*)(&O[base1 + c]) = make_float2(acc2[mt][nt][2], acc2[mt][nt][3]);
            }
        }
    }
}

// ---------------- launcher ----------------
#define K1_SMEM_BYTES (4 * 128 * RS1 * 2)

extern "C" void kernel_launch(void* const* d_in, const int* in_sizes, int n_in,
                              void* d_out, int out_size) {
    const float* inputs = (const float*)d_in[0];
    const void*  masks  = d_in[1];
    const float* emb    = (const float*)d_in[2];
    const float* wkey   = (const float*)d_in[3];
    float* out = (float*)d_out;
    (void)in_sizes; (void)n_in; (void)out_size;

    cudaFuncSetAttribute(k_keyproj, cudaFuncAttributeMaxDynamicSharedMemorySize, K1_SMEM_BYTES);
    cudaFuncSetAttribute(k_fused,   cudaFuncAttributeMaxDynamicSharedMemorySize, F_SMEM_BYTES);

    __half* d_xhc; cudaGetSymbolAddress((void**)&d_xhc, g_xhc);
    __half* d_xth; cudaGetSymbolAddress((void**)&d_xth, g_xth);
    __half* d_eh;  cudaGetSymbolAddress((void**)&d_eh,  g_eh);
    __half* d_wh;  cudaGetSymbolAddress((void**)&d_wh,  g_wh);

    k_scan<<<Bdim, 512>>>(masks);
    k_cvt2<<<512, 256>>>((const float4*)emb,  (uint4*)d_eh, Ldim * Hdim / 8,
                         (const float4*)wkey, (uint4*)d_wh, Hdim * Hdim / 8);
    k_gtr<<<dim3(Hdim / 32, Sdim / 32, Bdim), dim3(32, 8)>>>(inputs, d_xth, d_xhc);
    k_keyproj<<<dim3(6, 32, 1), 256, K1_SMEM_BYTES>>>(d_xhc, d_wh);
    k_fused<<<dim3(Ldim / 64, Bdim), 512, F_SMEM_BYTES>>>(d_eh, d_xth, out);
}

// round 15
// speedup vs baseline: 1.3276x; 1.0020x over previous
#include <cuda_runtime.h>
#include <cuda_fp16.h>
#include <cstdint>

#define Bdim 8
#define Sdim 512
#define Hdim 768
#define Ldim 8192

// scratch (static device globals: allocation-free)
__device__ __half g_xhc[Bdim * Sdim * Hdim];                // gathered-compacted inputs fp16 [B,j,H]
__device__ __half g_xth[Bdim * Hdim * Sdim];                // gathered-compacted inputs^T [B,H,j] fp16
__device__ __half g_eh[Ldim * Hdim];                        // label_embedding fp16
__device__ __half g_wh[Hdim * Hdim];                        // W_key fp16
__device__ __half g_akh[Bdim * Sdim * Hdim];                // attn_key fp16 (compacted rows)
__device__ int    g_idx[Bdim * Sdim];                       // compaction index per batch
__device__ int    g_nv[Bdim];                               // valid count per batch

// ---------------- PTX helpers ----------------
__device__ __forceinline__ void mma_f16(float* c, const uint32_t* a, const uint32_t* b) {
    asm volatile(
        "mma.sync.aligned.m16n8k16.row.col.f32.f16.f16.f32 "
        "{%0,%1,%2,%3}, {%4,%5,%6,%7}, {%8,%9}, {%0,%1,%2,%3};\n"
        : "+f"(c[0]), "+f"(c[1]), "+f"(c[2]), "+f"(c[3])
        : "r"(a[0]), "r"(a[1]), "r"(a[2]), "r"(a[3]), "r"(b[0]), "r"(b[1]));
}

__device__ __forceinline__ void ldsm_x4(uint32_t& r0, uint32_t& r1, uint32_t& r2,
                                        uint32_t& r3, uint32_t addr) {
    asm volatile("ldmatrix.sync.aligned.m8n8.x4.shared.b16 {%0,%1,%2,%3}, [%4];"
                 : "=r"(r0), "=r"(r1), "=r"(r2), "=r"(r3) : "r"(addr));
}

__device__ __forceinline__ void cp16(uint32_t s, const void* g) {
    asm volatile("cp.async.cg.shared.global [%0], [%1], 16;\n" :: "r"(s), "l"(g));
}
__device__ __forceinline__ void cp_commit() { asm volatile("cp.async.commit_group;\n"); }
__device__ __forceinline__ void cp_wait1()  { asm volatile("cp.async.wait_group 1;\n"); }
__device__ __forceinline__ void cp_wait0()  { asm volatile("cp.async.wait_group 0;\n"); }

// ---------------- mask scan (with inline dtype detection) ----------------
__global__ void k_scan(const void* __restrict__ masks) {
    __shared__ int sc[512];
    int b = blockIdx.x, t = threadIdx.x;
    const unsigned* mw = (const unsigned*)masks;
    int bad = (mw[t * 2] > 1u) || (mw[t * 2 + 1] > 1u);
    int is32 = __syncthreads_or(bad) ? 0 : 1;
    unsigned v = is32 ? (unsigned)((const int*)masks)[b * Sdim + t]
                      : (unsigned)((const unsigned char*)masks)[b * Sdim + t];
    int m = v ? 1 : 0;
    sc[t] = m;
    __syncthreads();
    for (int off = 1; off < 512; off <<= 1) {
        int x = (t >= off) ? sc[t - off] : 0;
        __syncthreads();
        sc[t] += x;
        __syncthreads();
    }
    int nv = sc[511];
    if (m) g_idx[b * Sdim + sc[t] - 1] = t;
    if (t >= nv) g_idx[b * Sdim + t] = 0;
    if (t == 0) g_nv[b] = nv;
}

// ---------------- prep: fp32 -> fp16 (two arrays, one launch) ----------------
__global__ void k_cvt2(const float4* __restrict__ s1, uint4* __restrict__ d1, int n1,
                       const float4* __restrict__ s2, uint4* __restrict__ d2, int n2) {
    int i = blockIdx.x * blockDim.x + threadIdx.x;
    int stride = gridDim.x * blockDim.x;
    for (; i < n1 + n2; i += stride) {
        const float4* src = (i < n1) ? s1 : s2;
        uint4* dst = (i < n1) ? d1 : d2;
        int j = (i < n1) ? i : i - n1;
        float4 a = src[2 * j], bq = src[2 * j + 1];
        __half2 h0 = __floats2half2_rn(a.x, a.y);
        __half2 h1 = __floats2half2_rn(a.z, a.w);
        __half2 h2 = __floats2half2_rn(bq.x, bq.y);
        __half2 h3 = __floats2half2_rn(bq.z, bq.w);
        uint4 o;
        o.x = *(uint32_t*)&h0; o.y = *(uint32_t*)&h1;
        o.z = *(uint32_t*)&h2; o.w = *(uint32_t*)&h3;
        dst[j] = o;
    }
}

// gather+convert: xhc[b][j][h] = half(X[b][idx[j]][h]);  xth[b][h][j] = transposed
__global__ void k_gtr(const float* __restrict__ X, __half* __restrict__ XT,
                      __half* __restrict__ XC) {
    __shared__ float t[32][33];
    int b = blockIdx.z;
    int j0 = blockIdx.y * 32, h0 = blockIdx.x * 32;
    int x = threadIdx.x, y = threadIdx.y;  // 32 x 8
    const float* srcb = X + (size_t)b * Sdim * Hdim;
#pragma unroll
    for (int i = 0; i < 32; i += 8) {
        int s = g_idx[b * Sdim + j0 + y + i];
        float v = srcb[(size_t)s * Hdim + h0 + x];
        t[y + i][x] = v;
        XC[((size_t)b * Sdim + j0 + y + i) * Hdim + h0 + x] = __float2half_rn(v);
    }
    __syncthreads();
    __half* dst = XT + ((size_t)b * Hdim + h0) * Sdim + j0;
#pragma unroll
    for (int i = 0; i < 32; i += 8)
        dst[(size_t)(y + i) * Sdim + x] = __float2half_rn(t[x][y + i]);
}

#define RS 72   // BK=64 row stride (halves); 9 == 1 mod 8 -> LDSM conflict-free

// ---------------- Kernel 1: attn_key(compacted) = xhc @ W_key^T ----------------
// BM=64 BN=128 BK=64, 256 threads (warps 2x4, WM=32 WN=32), 2-stage, nv skip.
#define K1_ASTG (64 * RS)
#define K1_BSTG (128 * RS)
#define K1_SMEM_BYTES (2 * (K1_ASTG + K1_BSTG) * 2)

__global__ __launch_bounds__(256) void k_keyproj(const __half* __restrict__ A,
                                                 const __half* __restrict__ W) {
    const int m0 = blockIdx.y * 64, n0 = blockIdx.x * 128;
    {
        int b = m0 >> 9, j0 = m0 & 511;
        if (j0 >= g_nv[b]) return;
    }
    extern __shared__ __align__(16) float smem[];
    uint32_t sb  = (uint32_t)__cvta_generic_to_shared(smem);
    const uint32_t sbA = sb;
    const uint32_t sbB = sb + 2u * K1_ASTG * 2u;

    const int tid  = threadIdx.x;
    const int lane = tid & 31, wid = tid >> 5;
    const int wm = wid & 1, wn = wid >> 1;   // 2 x 4
    const int tg = lane & 3, gid = lane >> 2;

    const int a_row = lane & 15, a_kh = (lane >> 4) << 3;
    const int b_row = ((lane >> 4) << 3) + (lane & 7), b_kh = ((lane >> 3) & 1) << 3;

    float acc[2][4][4];
#pragma unroll
    for (int i = 0; i < 2; i++)
#pragma unroll
        for (int j = 0; j < 4; j++)
#pragma unroll
            for (int r = 0; r < 4; r++) acc[i][j][r] = 0.f;

    auto fill = [&](int st, int kt) {
#pragma unroll
        for (int i = 0; i < 2; i++) {       // A: 64 rows x 8 chunks = 512 cp16
            int idx = tid + i * 256;
            int r = idx >> 3, c = (idx & 7) * 8;
            cp16(sbA + (uint32_t)(st * K1_ASTG + r * RS + c) * 2u,
                 A + (size_t)(m0 + r) * Hdim + kt * 64 + c);
        }
#pragma unroll
        for (int i = 0; i < 4; i++) {       // B: 128 rows x 8 chunks = 1024 cp16
            int idx = tid + i * 256;
            int r = idx >> 3, c = (idx & 7) * 8;
            cp16(sbB + (uint32_t)(st * K1_BSTG + r * RS + c) * 2u,
                 W + (size_t)(n0 + r) * Hdim + kt * 64 + c);
        }
        cp_commit();
    };

    const int KT = Hdim / 64;  // 12
    fill(0, 0);
#pragma unroll 1
    for (int kt = 0; kt < KT; ++kt) {
        int cur = kt & 1;
        if (kt + 1 < KT) { fill(cur ^ 1, kt + 1); cp_wait1(); }
        else             { cp_wait0(); }
        __syncthreads();
        const uint32_t aBase = sbA + (uint32_t)(cur * K1_ASTG) * 2u;
        const uint32_t bBase = sbB + (uint32_t)(cur * K1_BSTG) * 2u;
#pragma unroll
        for (int kk = 0; kk < 4; ++kk) {
            uint32_t af[2][4], bf[4][2];
#pragma unroll
            for (int mt = 0; mt < 2; ++mt)
                ldsm_x4(af[mt][0], af[mt][1], af[mt][2], af[mt][3],
                        aBase + (uint32_t)(((wm * 32 + mt * 16 + a_row) * RS + kk * 16 + a_kh) * 2));
#pragma unroll
            for (int p = 0; p < 2; ++p)
                ldsm_x4(bf[2 * p][0], bf[2 * p][1], bf[2 * p + 1][0], bf[2 * p + 1][1],
                        bBase + (uint32_t)(((wn * 32 + p * 16 + b_row) * RS + kk * 16 + b_kh) * 2));
#pragma unroll
            for (int mt = 0; mt < 2; ++mt)
#pragma unroll
                for (int nt = 0; nt < 4; ++nt)
                    mma_f16(acc[mt][nt], af[mt], bf[nt]);
        }
        __syncthreads();
    }
#pragma unroll
    for (int mt = 0; mt < 2; ++mt) {
        int r = m0 + wm * 32 + mt * 16 + gid;
#pragma unroll
        for (int nt = 0; nt < 4; ++nt) {
            int c = n0 + wn * 32 + nt * 8 + tg * 2;
            *(__half2*)(&g_akh[(size_t)r * Hdim + c]) =
                __floats2half2_rn(acc[mt][nt][0], acc[mt][nt][1]);
            *(__half2*)(&g_akh[(size_t)(r + 8) * Hdim + c]) =
                __floats2half2_rn(acc[mt][nt][2], acc[mt][nt][3]);
        }
    }
}

// ---------------- Fused Kernel (compacted S, 512 threads, BK=64) -----------
// Phase 1: scores 64 x nv; warps 2x8; warp wn owns interleaved tiles t = 8p+wn.
// Phase 2: out[64,768] = probs @ Xc; 2 H-halves of 384; warps 2x8 (WN=48).
#define P_RS 520
#define F_ASTG (64 * RS)
#define F_BSTG (512 * RS)
#define F_B_OFF (2 * F_ASTG)
#define F_XT_OFF (64 * P_RS)
#define F_XTSTG (384 * RS)
#define F_RED_BYTE (2 * (F_XT_OFF + 2 * F_XTSTG))
#define F_SMEM_BYTES (F_RED_BYTE + 64 * 8 * 4 + 16)

__global__ __launch_bounds__(512) void k_fused(const __half* __restrict__ E,
                                               const __half* __restrict__ XT,
                                               float* __restrict__ O) {
    extern __shared__ __align__(16) float smem[];
    uint32_t sb = (uint32_t)__cvta_generic_to_shared(smem);
    float* red = (float*)((char*)smem + F_RED_BYTE);

    const int tid  = threadIdx.x;
    const int lane = tid & 31, wid = tid >> 5;
    const int wm = wid & 1, wn = wid >> 1;  // 2 x 8
    const int tg = lane & 3, gid = lane >> 2;
    const int b  = blockIdx.y;
    const int m0 = blockIdx.x * 64;
    const __half* Bt = g_akh + (size_t)b * Sdim * Hdim;   // compacted rows
    const int nv = g_nv[b];

    const int a_row = lane & 15, a_kh = (lane >> 4) << 3;
    const int b_row = ((lane >> 4) << 3) + (lane & 7), b_kh = ((lane >> 3) & 1) << 3;

    const uint32_t sbA = sb;
    const uint32_t sbB = sb + (uint32_t)F_B_OFF * 2u;

    // ================= Phase 1: scores + softmax =================
    float acc[2][8][4];
#pragma unroll
    for (int i = 0; i < 2; i++)
#pragma unroll
        for (int j = 0; j < 8; j++)
#pragma unroll
            for (int r = 0; r < 4; r++) acc[i][j][r] = 0.f;

    auto fill1 = [&](int st, int kt) {
        {   // A: 64 rows x 8 chunks = 512 cp16
            int r = tid >> 3, c = (tid & 7) * 8;
            cp16(sbA + (uint32_t)(st * F_ASTG + r * RS + c) * 2u,
                 E + (size_t)(m0 + r) * Hdim + kt * 64 + c);
        }
#pragma unroll 1
        for (int i = 0; i < 8; i++) {  // B rows in 64-row blocks; uniform break at nv
            if (i * 64 >= nv) break;
            int idx = tid + i * 512;
            int r = idx >> 3, c = (idx & 7) * 8;
            if (r < nv)
                cp16(sbB + (uint32_t)(st * F_BSTG + r * RS + c) * 2u,
                     Bt + (size_t)r * Hdim + kt * 64 + c);
        }
        cp_commit();
    };

    const int KT = Hdim / 64;  // 12
    fill1(0, 0);
#pragma unroll 1
    for (int kt = 0; kt < KT; ++kt) {
        int cur = kt & 1;
        if (kt + 1 < KT) { fill1(cur ^ 1, kt + 1); cp_wait1(); }
        else             { cp_wait0(); }
        __syncthreads();
        const uint32_t aBase = sbA + (uint32_t)(cur * F_ASTG) * 2u;
        const uint32_t bBase = sbB + (uint32_t)(cur * F_BSTG) * 2u;
#pragma unroll
        for (int kk = 0; kk < 4; ++kk) {
            uint32_t af[2][4], bf[8][2];
#pragma unroll
            for (int mt = 0; mt < 2; ++mt)
                ldsm_x4(af[mt][0], af[mt][1], af[mt][2], af[mt][3],
                        aBase + (uint32_t)(((wm * 32 + mt * 16 + a_row) * RS + kk * 16 + a_kh) * 2));
#pragma unroll
            for (int p = 0; p < 4; ++p) {
                int c0 = (8 * p + wn) * 16;   // interleaved tile -> balanced skip
                if (c0 < nv) {
                    ldsm_x4(bf[2 * p][0], bf[2 * p][1], bf[2 * p + 1][0], bf[2 * p + 1][1],
                            bBase + (uint32_t)(((c0 + b_row) * RS + kk * 16 + b_kh) * 2));
#pragma unroll
                    for (int mt = 0; mt < 2; ++mt) {
                        mma_f16(acc[mt][2 * p],     af[mt], bf[2 * p]);
                        mma_f16(acc[mt][2 * p + 1], af[mt], bf[2 * p + 1]);
                    }
                }
            }
        }
        __syncthreads();
    }

    // softmax over compacted columns: col(nt) = (8*(nt>>1)+wn)*16 + (nt&1)*8 + tg*2
    float mx[4] = {-1e30f, -1e30f, -1e30f, -1e30f};
#pragma unroll
    for (int mt = 0; mt < 2; ++mt)
#pragma unroll
        for (int nt = 0; nt < 8; ++nt) {
            int col = (8 * (nt >> 1) + wn) * 16 + (nt & 1) * 8 + tg * 2;
            if (col >= nv)     { acc[mt][nt][0] = -1e30f; acc[mt][nt][2] = -1e30f; }
            if (col + 1 >= nv) { acc[mt][nt][1] = -1e30f; acc[mt][nt][3] = -1e30f; }
            mx[mt * 2]     = fmaxf(mx[mt * 2],     fmaxf(acc[mt][nt][0], acc[mt][nt][1]));
            mx[mt * 2 + 1] = fmaxf(mx[mt * 2 + 1], fmaxf(acc[mt][nt][2], acc[mt][nt][3]));
        }
#pragma unroll
    for (int j = 0; j < 4; ++j) {
        mx[j] = fmaxf(mx[j], __shfl_xor_sync(0xffffffffu, mx[j], 1));
        mx[j] = fmaxf(mx[j], __shfl_xor_sync(0xffffffffu, mx[j], 2));
    }
    if (tg == 0) {
#pragma unroll
        for (int j = 0; j < 4; ++j) {
            int rl = wm * 32 + (j >> 1) * 16 + (j & 1) * 8 + gid;
            red[rl * 8 + wn] = mx[j];
        }
    }
    __syncthreads();
    float gmx[4];
#pragma unroll
    for (int j = 0; j < 4; ++j) {
        int rl = wm * 32 + (j >> 1) * 16 + (j & 1) * 8 + gid;
        float m = -1e30f;
#pragma unroll
        for (int w = 0; w < 8; ++w) m = fmaxf(m, red[rl * 8 + w]);
        gmx[j] = m;
    }
    __syncthreads();

    float sme[4] = {0.f, 0.f, 0.f, 0.f};
#pragma unroll
    for (int mt = 0; mt < 2; ++mt)
#pragma unroll
        for (int nt = 0; nt < 8; ++nt) {
            float e0 = __expf(acc[mt][nt][0] - gmx[mt * 2]);
            float e1 = __expf(acc[mt][nt][1] - gmx[mt * 2]);
            float e2 = __expf(acc[mt][nt][2] - gmx[mt * 2 + 1]);
            float e3 = __expf(acc[mt][nt][3] - gmx[mt * 2 + 1]);
            acc[mt][nt][0] = e0; acc[mt][nt][1] = e1;
            acc[mt][nt][2] = e2; acc[mt][nt][3] = e3;
            sme[mt * 2]     += e0 + e1;
            sme[mt * 2 + 1] += e2 + e3;
        }
#pragma unroll
    for (int j = 0; j < 4; ++j) {
        sme[j] += __shfl_xor_sync(0xffffffffu, sme[j], 1);
        sme[j] += __shfl_xor_sync(0xffffffffu, sme[j], 2);
    }
    if (tg == 0) {
#pragma unroll
        for (int j = 0; j < 4; ++j) {
            int rl = wm * 32 + (j >> 1) * 16 + (j & 1) * 8 + gid;
            red[rl * 8 + wn] = sme[j];
        }
    }
    __syncthreads();
    float inv[4];
#pragma unroll
    for (int j = 0; j < 4; ++j) {
        int rl = wm * 32 + (j >> 1) * 16 + (j & 1) * 8 + gid;
        float s = 0.f;
#pragma unroll
        for (int w = 0; w < 8; ++w) s += red[rl * 8 + w];
        inv[j] = 1.f / s;
    }

    // probs -> smem fp16 (aliases dead phase-1 stages); masked cols exactly 0
    __half* probs = (__half*)smem;
#pragma unroll
    for (int mt = 0; mt < 2; ++mt) {
        int r0 = wm * 32 + mt * 16 + gid;
        int r1 = r0 + 8;
#pragma unroll
        for (int nt = 0; nt < 8; ++nt) {
            int col = (8 * (nt >> 1) + wn) * 16 + (nt & 1) * 8 + tg * 2;
            *(__half2*)(&probs[r0 * P_RS + col]) =
                __floats2half2_rn(acc[mt][nt][0] * inv[mt * 2], acc[mt][nt][1] * inv[mt * 2]);
            *(__half2*)(&probs[r1 * P_RS + col]) =
                __floats2half2_rn(acc[mt][nt][2] * inv[mt * 2 + 1], acc[mt][nt][3] * inv[mt * 2 + 1]);
        }
    }
    __syncthreads();

    // ================= Phase 2: out = probs @ Xc (K = nv, BK=64) ============
    const uint32_t pB   = sb;
    const uint32_t sbXT = sb + (uint32_t)F_XT_OFF * 2u;
    const int KT2 = (nv + 63) >> 6;   // <= 8

#pragma unroll 1
    for (int ht = 0; ht < 2; ++ht) {
        const __half* Xg = XT + ((size_t)b * Hdim + ht * 384) * Sdim;

        float acc2[2][6][4];
#pragma unroll
        for (int i = 0; i < 2; i++)
#pragma unroll
            for (int j = 0; j < 6; j++)
#pragma unroll
                for (int r = 0; r < 4; r++) acc2[i][j][r] = 0.f;

        auto fill2 = [&](int st, int kt) {
#pragma unroll
            for (int i = 0; i < 6; i++) {  // 384 rows x 8 chunks = 3072 cp16
                int idx = tid + i * 512;
                int r = idx >> 3, c = (idx & 7) * 8;
                cp16(sbXT + (uint32_t)(st * F_XTSTG + r * RS + c) * 2u,
                     Xg + (size_t)r * Sdim + kt * 64 + c);
            }
            cp_commit();
        };

        fill2(0, 0);
#pragma unroll 1
        for (int kt = 0; kt < KT2; ++kt) {
            int cur = kt & 1;
            if (kt + 1 < KT2) { fill2(cur ^ 1, kt + 1); cp_wait1(); }
            else              { cp_wait0(); }
            __syncthreads();
            const uint32_t xBase = sbXT + (uint32_t)(cur * F_XTSTG) * 2u;
#pragma unroll
            for (int kk = 0; kk < 4; ++kk) {
                uint32_t af[2][4], bf[6][2];
#pragma unroll
                for (int mt = 0; mt < 2; ++mt)
                    ldsm_x4(af[mt][0], af[mt][1], af[mt][2], af[mt][3],
                            pB + (uint32_t)(((wm * 32 + mt * 16 + a_row) * P_RS +
                                             kt * 64 + kk * 16 + a_kh) * 2));
#pragma unroll
                for (int p = 0; p < 3; ++p)
                    ldsm_x4(bf[2 * p][0], bf[2 * p][1], bf[2 * p + 1][0], bf[2 * p + 1][1],
                            xBase + (uint32_t)(((wn * 48 + p * 16 + b_row) * RS + kk * 16 + b_kh) * 2));
#pragma unroll
                for (int mt = 0; mt < 2; ++mt)
#pragma unroll
                    for (int nt = 0; nt < 6; ++nt)
                        mma_f16(acc2[mt][nt], af[mt], bf[nt]);
            }
            __syncthreads();
        }

        // epilogue: write this H-half
#pragma unroll
        for (int mt = 0; mt < 2; ++mt) {
            int r = m0 + wm * 32 + mt * 16 + gid;
            size_t base0 = ((size_t)b * Ldim + r) * Hdim;
            size_t base1 = ((size_t)b * Ldim + r + 8) * Hdim;
#pragma unroll
            for (int nt = 0; nt < 6; ++nt) {
                int c = ht * 384 + wn * 48 + nt * 8 + tg * 2;
                *(float2*)(&O[base0 + c]) = make_float2(acc2[mt][nt][0], acc2[mt][nt][1]);
                *(float2*)(&O[base1 + c]) = make_float2(acc2[mt][nt][2], acc2[mt][nt][3]);
            }
        }
    }
}

// ---------------- launcher ----------------
extern "C" void kernel_launch(void* const* d_in, const int* in_sizes, int n_in,
                              void* d_out, int out_size) {
    const float* inputs = (const float*)d_in[0];
    const void*  masks  = d_in[1];
    const float* emb    = (const float*)d_in[2];
    const float* wkey   = (const float*)d_in[3];
    float* out = (float*)d_out;
    (void)in_sizes; (void)n_in; (void)out_size;

    cudaFuncSetAttribute(k_keyproj, cudaFuncAttributeMaxDynamicSharedMemorySize, K1_SMEM_BYTES);
    cudaFuncSetAttribute(k_fused,   cudaFuncAttributeMaxDynamicSharedMemorySize, F_SMEM_BYTES);

    __half* d_xhc; cudaGetSymbolAddress((void**)&d_xhc, g_xhc);
    __half* d_xth; cudaGetSymbolAddress((void**)&d_xth, g_xth);
    __half* d_eh;  cudaGetSymbolAddress((void**)&d_eh,  g_eh);
    __half* d_wh;  cudaGetSymbolAddress((void**)&d_wh,  g_wh);

    k_scan<<<Bdim, 512>>>(masks);
    k_cvt2<<<512, 256>>>((const float4*)emb,  (uint4*)d_eh, Ldim * Hdim / 8,
                         (const float4*)wkey, (uint4*)d_wh, Hdim * Hdim / 8);
    k_gtr<<<dim3(Hdim / 32, Sdim / 32, Bdim), dim3(32, 8)>>>(inputs, d_xth, d_xhc);
    k_keyproj<<<dim3(6, 64, 1), 256, K1_SMEM_BYTES>>>(d_xhc, d_wh);
    k_fused<<<dim3(Ldim / 64, Bdim), 512, F_SMEM_BYTES>>>(d_eh, d_xth, out);
}

// round 16
// speedup vs baseline: 1.3692x; 1.0313x over previous
#include <cuda_runtime.h>
#include <cuda_fp16.h>
#include <cstdint>

#define Bdim 8
#define Sdim 512
#define Hdim 768
#define Ldim 8192

// scratch (static device globals: allocation-free)
__device__ __half g_xhc[Bdim * Sdim * Hdim];                // gathered-compacted inputs fp16 [B,j,H]
__device__ __half g_xth[Bdim * Hdim * Sdim];                // gathered-compacted inputs^T [B,H,j] fp16
__device__ __half g_eh[Ldim * Hdim];                        // label_embedding fp16
__device__ __half g_wh[Hdim * Hdim];                        // W_key fp16
__device__ __half g_akh[Bdim * Sdim * Hdim];                // attn_key fp16 (compacted rows)
__device__ int    g_idx[Bdim * Sdim];                       // compaction index per batch
__device__ int    g_nv[Bdim];                               // valid count per batch

// ---------------- PTX helpers ----------------
__device__ __forceinline__ void mma_f16(float* c, const uint32_t* a, const uint32_t* b) {
    asm volatile(
        "mma.sync.aligned.m16n8k16.row.col.f32.f16.f16.f32 "
        "{%0,%1,%2,%3}, {%4,%5,%6,%7}, {%8,%9}, {%0,%1,%2,%3};\n"
        : "+f"(c[0]), "+f"(c[1]), "+f"(c[2]), "+f"(c[3])
        : "r"(a[0]), "r"(a[1]), "r"(a[2]), "r"(a[3]), "r"(b[0]), "r"(b[1]));
}

__device__ __forceinline__ void ldsm_x4(uint32_t& r0, uint32_t& r1, uint32_t& r2,
                                        uint32_t& r3, uint32_t addr) {
    asm volatile("ldmatrix.sync.aligned.m8n8.x4.shared.b16 {%0,%1,%2,%3}, [%4];"
                 : "=r"(r0), "=r"(r1), "=r"(r2), "=r"(r3) : "r"(addr));
}

__device__ __forceinline__ void cp16(uint32_t s, const void* g) {
    asm volatile("cp.async.cg.shared.global [%0], [%1], 16;\n" :: "r"(s), "l"(g));
}
__device__ __forceinline__ void cp_commit() { asm volatile("cp.async.commit_group;\n"); }
__device__ __forceinline__ void cp_wait1()  { asm volatile("cp.async.wait_group 1;\n"); }
__device__ __forceinline__ void cp_wait0()  { asm volatile("cp.async.wait_group 0;\n"); }

// ---------------- mask scan (with inline dtype detection) ----------------
__global__ void k_scan(const void* __restrict__ masks) {
    __shared__ int sc[512];
    int b = blockIdx.x, t = threadIdx.x;
    const unsigned* mw = (const unsigned*)masks;
    int bad = (mw[t * 2] > 1u) || (mw[t * 2 + 1] > 1u);
    int is32 = __syncthreads_or(bad) ? 0 : 1;
    unsigned v = is32 ? (unsigned)((const int*)masks)[b * Sdim + t]
                      : (unsigned)((const unsigned char*)masks)[b * Sdim + t];
    int m = v ? 1 : 0;
    sc[t] = m;
    __syncthreads();
    for (int off = 1; off < 512; off <<= 1) {
        int x = (t >= off) ? sc[t - off] : 0;
        __syncthreads();
        sc[t] += x;
        __syncthreads();
    }
    int nv = sc[511];
    if (m) g_idx[b * Sdim + sc[t] - 1] = t;
    if (t >= nv) g_idx[b * Sdim + t] = 0;
    if (t == 0) g_nv[b] = nv;
}

// ---- merged gather-transpose-convert + emb/wkey fp32->fp16 conversion ----
// grid (24, 16, Bdim+1): z < Bdim -> gtr for batch z; z == Bdim -> cvt plane.
__global__ void k_gtrc(const float* __restrict__ X, __half* __restrict__ XT,
                       __half* __restrict__ XC,
                       const float4* __restrict__ s1, uint4* __restrict__ d1, int n1,
                       const float4* __restrict__ s2, uint4* __restrict__ d2, int n2) {
    if (blockIdx.z == Bdim) {
        int lb = blockIdx.x + gridDim.x * blockIdx.y;
        int t  = threadIdx.y * 32 + threadIdx.x;
        int i = lb * 256 + t;
        int stride = gridDim.x * gridDim.y * 256;
        for (; i < n1 + n2; i += stride) {
            const float4* src = (i < n1) ? s1 : s2;
            uint4* dst = (i < n1) ? d1 : d2;
            int j = (i < n1) ? i : i - n1;
            float4 a = src[2 * j], bq = src[2 * j + 1];
            __half2 h0 = __floats2half2_rn(a.x, a.y);
            __half2 h1 = __floats2half2_rn(a.z, a.w);
            __half2 h2 = __floats2half2_rn(bq.x, bq.y);
            __half2 h3 = __floats2half2_rn(bq.z, bq.w);
            uint4 o;
            o.x = *(uint32_t*)&h0; o.y = *(uint32_t*)&h1;
            o.z = *(uint32_t*)&h2; o.w = *(uint32_t*)&h3;
            dst[j] = o;
        }
        return;
    }
    __shared__ float t[32][33];
    int b = blockIdx.z;
    int j0 = blockIdx.y * 32, h0 = blockIdx.x * 32;
    int x = threadIdx.x, y = threadIdx.y;  // 32 x 8
    const float* srcb = X + (size_t)b * Sdim * Hdim;
#pragma unroll
    for (int i = 0; i < 32; i += 8) {
        int s = g_idx[b * Sdim + j0 + y + i];
        float v = srcb[(size_t)s * Hdim + h0 + x];
        t[y + i][x] = v;
        XC[((size_t)b * Sdim + j0 + y + i) * Hdim + h0 + x] = __float2half_rn(v);
    }
    __syncthreads();
    __half* dst = XT + ((size_t)b * Hdim + h0) * Sdim + j0;
#pragma unroll
    for (int i = 0; i < 32; i += 8)
        dst[(size_t)(y + i) * Sdim + x] = __float2half_rn(t[x][y + i]);
}

#define RS 72   // BK=64 row stride (halves); stride 144B -> LDSM conflict-free

// ---------------- Kernel 1: attn_key(compacted) = xhc @ W_key^T ----------------
// BM=64 BN=128 BK=64, 256 threads (warps 2x4, WM=32 WN=32), 2-stage, nv skip.
#define K1_ASTG (64 * RS)
#define K1_BSTG (128 * RS)
#define K1_SMEM_BYTES (2 * (K1_ASTG + K1_BSTG) * 2)

__global__ __launch_bounds__(256) void k_keyproj(const __half* __restrict__ A,
                                                 const __half* __restrict__ W) {
    const int m0 = blockIdx.y * 64, n0 = blockIdx.x * 128;
    {
        int b = m0 >> 9, j0 = m0 & 511;
        if (j0 >= g_nv[b]) return;
    }
    extern __shared__ __align__(16) float smem[];
    uint32_t sb  = (uint32_t)__cvta_generic_to_shared(smem);
    const uint32_t sbA = sb;
    const uint32_t sbB = sb + 2u * K1_ASTG * 2u;

    const int tid  = threadIdx.x;
    const int lane = tid & 31, wid = tid >> 5;
    const int wm = wid & 1, wn = wid >> 1;   // 2 x 4
    const int tg = lane & 3, gid = lane >> 2;

    const int a_row = lane & 15, a_kh = (lane >> 4) << 3;
    const int b_row = ((lane >> 4) << 3) + (lane & 7), b_kh = ((lane >> 3) & 1) << 3;

    float acc[2][4][4];
#pragma unroll
    for (int i = 0; i < 2; i++)
#pragma unroll
        for (int j = 0; j < 4; j++)
#pragma unroll
            for (int r = 0; r < 4; r++) acc[i][j][r] = 0.f;

    auto fill = [&](int st, int kt) {
#pragma unroll
        for (int i = 0; i < 2; i++) {
            int idx = tid + i * 256;
            int r = idx >> 3, c = (idx & 7) * 8;
            cp16(sbA + (uint32_t)(st * K1_ASTG + r * RS + c) * 2u,
                 A + (size_t)(m0 + r) * Hdim + kt * 64 + c);
        }
#pragma unroll
        for (int i = 0; i < 4; i++) {
            int idx = tid + i * 256;
            int r = idx >> 3, c = (idx & 7) * 8;
            cp16(sbB + (uint32_t)(st * K1_BSTG + r * RS + c) * 2u,
                 W + (size_t)(n0 + r) * Hdim + kt * 64 + c);
        }
        cp_commit();
    };

    const int KT = Hdim / 64;  // 12
    fill(0, 0);
#pragma unroll 1
    for (int kt = 0; kt < KT; ++kt) {
        int cur = kt & 1;
        if (kt + 1 < KT) { fill(cur ^ 1, kt + 1); cp_wait1(); }
        else             { cp_wait0(); }
        __syncthreads();
        const uint32_t aBase = sbA + (uint32_t)(cur * K1_ASTG) * 2u;
        const uint32_t bBase = sbB + (uint32_t)(cur * K1_BSTG) * 2u;
#pragma unroll
        for (int kk = 0; kk < 4; ++kk) {
            uint32_t af[2][4], bf[4][2];
#pragma unroll
            for (int mt = 0; mt < 2; ++mt)
                ldsm_x4(af[mt][0], af[mt][1], af[mt][2], af[mt][3],
                        aBase + (uint32_t)(((wm * 32 + mt * 16 + a_row) * RS + kk * 16 + a_kh) * 2));
#pragma unroll
            for (int p = 0; p < 2; ++p)
                ldsm_x4(bf[2 * p][0], bf[2 * p][1], bf[2 * p + 1][0], bf[2 * p + 1][1],
                        bBase + (uint32_t)(((wn * 32 + p * 16 + b_row) * RS + kk * 16 + b_kh) * 2));
#pragma unroll
            for (int mt = 0; mt < 2; ++mt)
#pragma unroll
                for (int nt = 0; nt < 4; ++nt)
                    mma_f16(acc[mt][nt], af[mt], bf[nt]);
        }
        __syncthreads();
    }
#pragma unroll
    for (int mt = 0; mt < 2; ++mt) {
        int r = m0 + wm * 32 + mt * 16 + gid;
#pragma unroll
        for (int nt = 0; nt < 4; ++nt) {
            int c = n0 + wn * 32 + nt * 8 + tg * 2;
            *(__half2*)(&g_akh[(size_t)r * Hdim + c]) =
                __floats2half2_rn(acc[mt][nt][0], acc[mt][nt][1]);
            *(__half2*)(&g_akh[(size_t)(r + 8) * Hdim + c]) =
                __floats2half2_rn(acc[mt][nt][2], acc[mt][nt][3]);
        }
    }
}

// ---------------- Fused Kernel (compacted S, 512 threads, BK=64) -----------
// Phase 1: 3-stage single-barrier pipeline; B stages hold 320 rows; column
//          passes cb in {0,320} (pass 2 only if nv>320 -- ~never).
// Phase 2: 3 H-tiles of 256; 3-stage single-barrier pipeline.
#define P_RS 520
#define F1_AST (64 * RS)
#define F1_BST (320 * RS)
#define F2_ST  (256 * RS)
#define F_XT_BYTE (64 * P_RS * 2)
#define F_RED_BYTE (F_XT_BYTE + 3 * F2_ST * 2)
#define F_SMEM_BYTES (F_RED_BYTE + 64 * 8 * 4 + 16)

__global__ __launch_bounds__(512) void k_fused(const __half* __restrict__ E,
                                               const __half* __restrict__ XT,
                                               float* __restrict__ O) {
    extern __shared__ __align__(16) float smem[];
    uint32_t sb = (uint32_t)__cvta_generic_to_shared(smem);
    float* red = (float*)((char*)smem + F_RED_BYTE);

    const int tid  = threadIdx.x;
    const int lane = tid & 31, wid = tid >> 5;
    const int wm = wid & 1, wn = wid >> 1;  // 2 x 8
    const int tg = lane & 3, gid = lane >> 2;
    const int b  = blockIdx.y;
    const int m0 = blockIdx.x * 64;
    const __half* Bt = g_akh + (size_t)b * Sdim * Hdim;   // compacted rows
    const int nv = g_nv[b];

    const int a_row = lane & 15, a_kh = (lane >> 4) << 3;
    const int b_row = ((lane >> 4) << 3) + (lane & 7), b_kh = ((lane >> 3) & 1) << 3;

    const uint32_t sbA1 = sb;
    const uint32_t sbB1 = sb + 3u * F1_AST * 2u;

    // ================= Phase 1: scores + softmax =================
    float acc[2][8][4];
#pragma unroll
    for (int i = 0; i < 2; i++)
#pragma unroll
        for (int j = 0; j < 8; j++)
#pragma unroll
            for (int r = 0; r < 4; r++) acc[i][j][r] = 0.f;

    const int KT = Hdim / 64;  // 12
#pragma unroll 1
    for (int pass = 0; pass < 2; ++pass) {
        int cb = pass * 320;
        if (cb >= nv) break;
        int cbe  = (nv < cb + 320) ? nv : (cb + 320);
        int rows = cbe - cb;

        auto fill1 = [&](int st, int kt) {
            {   // A: 64 rows x 8 chunks = 512 cp16
                int r = tid >> 3, c = (tid & 7) * 8;
                cp16(sbA1 + (uint32_t)(st * F1_AST + r * RS + c) * 2u,
                     E + (size_t)(m0 + r) * Hdim + kt * 64 + c);
            }
#pragma unroll 1
            for (int i = 0; i < 5; i++) {
                if (i * 64 >= rows) break;
                int idx = tid + i * 512;
                int r = idx >> 3, c = (idx & 7) * 8;
                if (r < rows)
                    cp16(sbB1 + (uint32_t)(st * F1_BST + r * RS + c) * 2u,
                         Bt + (size_t)(cb + r) * Hdim + kt * 64 + c);
            }
            cp_commit();
        };

        fill1(0, 0);
        fill1(1, 1);
        cp_wait1();
        __syncthreads();

#pragma unroll 1
        for (int kt = 0; kt < KT; ++kt) {
            int cur = kt % 3;
            const uint32_t aBase = sbA1 + (uint32_t)(cur * F1_AST) * 2u;
            const uint32_t bBase = sbB1 + (uint32_t)(cur * F1_BST) * 2u;
#pragma unroll
            for (int kk = 0; kk < 4; ++kk) {
                uint32_t af[2][4], bf[8][2];
#pragma unroll
                for (int mt = 0; mt < 2; ++mt)
                    ldsm_x4(af[mt][0], af[mt][1], af[mt][2], af[mt][3],
                            aBase + (uint32_t)(((wm * 32 + mt * 16 + a_row) * RS + kk * 16 + a_kh) * 2));
#pragma unroll
                for (int p = 0; p < 4; ++p) {
                    int c0 = (8 * p + wn) * 16;   // absolute column tile
                    if (c0 >= cb && c0 < cbe) {
                        ldsm_x4(bf[2 * p][0], bf[2 * p][1], bf[2 * p + 1][0], bf[2 * p + 1][1],
                                bBase + (uint32_t)(((c0 - cb + b_row) * RS + kk * 16 + b_kh) * 2));
#pragma unroll
                        for (int mt = 0; mt < 2; ++mt) {
                            mma_f16(acc[mt][2 * p],     af[mt], bf[2 * p]);
                            mma_f16(acc[mt][2 * p + 1], af[mt], bf[2 * p + 1]);
                        }
                    }
                }
            }
            if (kt + 2 < KT) fill1((kt + 2) % 3, kt + 2);
            if (kt + 1 < KT) { if (kt + 2 < KT) cp_wait1(); else cp_wait0(); }
            __syncthreads();
        }
    }

    // softmax over compacted columns: col(nt) = (8*(nt>>1)+wn)*16 + (nt&1)*8 + tg*2
    float mx[4] = {-1e30f, -1e30f, -1e30f, -1e30f};
#pragma unroll
    for (int mt = 0; mt < 2; ++mt)
#pragma unroll
        for (int nt = 0; nt < 8; ++nt) {
            int col = (8 * (nt >> 1) + wn) * 16 + (nt & 1) * 8 + tg * 2;
            if (col >= nv)     { acc[mt][nt][0] = -1e30f; acc[mt][nt][2] = -1e30f; }
            if (col + 1 >= nv) { acc[mt][nt][1] = -1e30f; acc[mt][nt][3] = -1e30f; }
            mx[mt * 2]     = fmaxf(mx[mt * 2],     fmaxf(acc[mt][nt][0], acc[mt][nt][1]));
            mx[mt * 2 + 1] = fmaxf(mx[mt * 2 + 1], fmaxf(acc[mt][nt][2], acc[mt][nt][3]));
        }
#pragma unroll
    for (int j = 0; j < 4; ++j) {
        mx[j] = fmaxf(mx[j], __shfl_xor_sync(0xffffffffu, mx[j], 1));
        mx[j] = fmaxf(mx[j], __shfl_xor_sync(0xffffffffu, mx[j], 2));
    }
    if (tg == 0) {
#pragma unroll
        for (int j = 0; j < 4; ++j) {
            int rl = wm * 32 + (j >> 1) * 16 + (j & 1) * 8 + gid;
            red[rl * 8 + wn] = mx[j];
        }
    }
    __syncthreads();
    float gmx[4];
#pragma unroll
    for (int j = 0; j < 4; ++j) {
        int rl = wm * 32 + (j >> 1) * 16 + (j & 1) * 8 + gid;
        float m = -1e30f;
#pragma unroll
        for (int w = 0; w < 8; ++w) m = fmaxf(m, red[rl * 8 + w]);
        gmx[j] = m;
    }
    __syncthreads();

    float sme[4] = {0.f, 0.f, 0.f, 0.f};
#pragma unroll
    for (int mt = 0; mt < 2; ++mt)
#pragma unroll
        for (int nt = 0; nt < 8; ++nt) {
            float e0 = __expf(acc[mt][nt][0] - gmx[mt * 2]);
            float e1 = __expf(acc[mt][nt][1] - gmx[mt * 2]);
            float e2 = __expf(acc[mt][nt][2] - gmx[mt * 2 + 1]);
            float e3 = __expf(acc[mt][nt][3] - gmx[mt * 2 + 1]);
            acc[mt][nt][0] = e0; acc[mt][nt][1] = e1;
            acc[mt][nt][2] = e2; acc[mt][nt][3] = e3;
            sme[mt * 2]     += e0 + e1;
            sme[mt * 2 + 1] += e2 + e3;
        }
#pragma unroll
    for (int j = 0; j < 4; ++j) {
        sme[j] += __shfl_xor_sync(0xffffffffu, sme[j], 1);
        sme[j] += __shfl_xor_sync(0xffffffffu, sme[j], 2);
    }
    if (tg == 0) {
#pragma unroll
        for (int j = 0; j < 4; ++j) {
            int rl = wm * 32 + (j >> 1) * 16 + (j & 1) * 8 + gid;
            red[rl * 8 + wn] = sme[j];
        }
    }
    __syncthreads();
    float inv[4];
#pragma unroll
    for (int j = 0; j < 4; ++j) {
        int rl = wm * 32 + (j >> 1) * 16 + (j & 1) * 8 + gid;
        float s = 0.f;
#pragma unroll
        for (int w = 0; w < 8; ++w) s += red[rl * 8 + w];
        inv[j] = 1.f / s;
    }

    // probs -> smem fp16 (aliases dead phase-1 stages); masked cols exactly 0
    __half* probs = (__half*)smem;
#pragma unroll
    for (int mt = 0; mt < 2; ++mt) {
        int r0 = wm * 32 + mt * 16 + gid;
        int r1 = r0 + 8;
#pragma unroll
        for (int nt = 0; nt < 8; ++nt) {
            int col = (8 * (nt >> 1) + wn) * 16 + (nt & 1) * 8 + tg * 2;
            *(__half2*)(&probs[r0 * P_RS + col]) =
                __floats2half2_rn(acc[mt][nt][0] * inv[mt * 2], acc[mt][nt][1] * inv[mt * 2]);
            *(__half2*)(&probs[r1 * P_RS + col]) =
                __floats2half2_rn(acc[mt][nt][2] * inv[mt * 2 + 1], acc[mt][nt][3] * inv[mt * 2 + 1]);
        }
    }
    __syncthreads();

    // ================= Phase 2: out = probs @ Xc (K = nv, BK=64) ============
    const uint32_t pB   = sb;
    const uint32_t sbXT = sb + (uint32_t)F_XT_BYTE;
    const int KT2 = (nv + 63) >> 6;   // <= 8

#pragma unroll 1
    for (int ht = 0; ht < 3; ++ht) {
        const __half* Xg = XT + ((size_t)b * Hdim + ht * 256) * Sdim;

        float acc2[2][4][4];
#pragma unroll
        for (int i = 0; i < 2; i++)
#pragma unroll
            for (int j = 0; j < 4; j++)
#pragma unroll
                for (int r = 0; r < 4; r++) acc2[i][j][r] = 0.f;

        auto fill2 = [&](int st, int kt) {
#pragma unroll
            for (int i = 0; i < 4; i++) {  // 256 rows x 8 chunks = 2048 cp16
                int idx = tid + i * 512;
                int r = idx >> 3, c = (idx & 7) * 8;
                cp16(sbXT + (uint32_t)(st * F2_ST + r * RS + c) * 2u,
                     Xg + (size_t)r * Sdim + kt * 64 + c);
            }
            cp_commit();
        };

        fill2(0, 0);
        if (KT2 > 1) { fill2(1, 1); cp_wait1(); }
        else         { cp_wait0(); }
        __syncthreads();

#pragma unroll 1
        for (int kt = 0; kt < KT2; ++kt) {
            int cur = kt % 3;
            const uint32_t xBase = sbXT + (uint32_t)(cur * F2_ST) * 2u;
#pragma unroll
            for (int kk = 0; kk < 4; ++kk) {
                uint32_t af[2][4], bf[4][2];
#pragma unroll
                for (int mt = 0; mt < 2; ++mt)
                    ldsm_x4(af[mt][0], af[mt][1], af[mt][2], af[mt][3],
                            pB + (uint32_t)(((wm * 32 + mt * 16 + a_row) * P_RS +
                                             kt * 64 + kk * 16 + a_kh) * 2));
#pragma unroll
                for (int p = 0; p < 2; ++p)
                    ldsm_x4(bf[2 * p][0], bf[2 * p][1], bf[2 * p + 1][0], bf[2 * p + 1][1],
                            xBase + (uint32_t)(((wn * 32 + p * 16 + b_row) * RS + kk * 16 + b_kh) * 2));
#pragma unroll
                for (int mt = 0; mt < 2; ++mt)
#pragma unroll
                    for (int nt = 0; nt < 4; ++nt)
                        mma_f16(acc2[mt][nt], af[mt], bf[nt]);
            }
            if (kt + 2 < KT2) fill2((kt + 2) % 3, kt + 2);
            if (kt + 1 < KT2) { if (kt + 2 < KT2) cp_wait1(); else cp_wait0(); }
            __syncthreads();
        }

        // epilogue: write this H-third
#pragma unroll
        for (int mt = 0; mt < 2; ++mt) {
            int r = m0 + wm * 32 + mt * 16 + gid;
            size_t base0 = ((size_t)b * Ldim + r) * Hdim;
            size_t base1 = ((size_t)b * Ldim + r + 8) * Hdim;
#pragma unroll
            for (int nt = 0; nt < 4; ++nt) {
                int c = ht * 256 + wn * 32 + nt * 8 + tg * 2;
                *(float2*)(&O[base0 + c]) = make_float2(acc2[mt][nt][0], acc2[mt][nt][1]);
                *(float2*)(&O[base1 + c]) = make_float2(acc2[mt][nt][2], acc2[mt][nt][3]);
            }
        }
    }
}

// ---------------- launcher ----------------
extern "C" void kernel_launch(void* const* d_in, const int* in_sizes, int n_in,
                              void* d_out, int out_size) {
    const float* inputs = (const float*)d_in[0];
    const void*  masks  = d_in[1];
    const float* emb    = (const float*)d_in[2];
    const float* wkey   = (const float*)d_in[3];
    float* out = (float*)d_out;
    (void)in_sizes; (void)n_in; (void)out_size;

    cudaFuncSetAttribute(k_keyproj, cudaFuncAttributeMaxDynamicSharedMemorySize, K1_SMEM_BYTES);
    cudaFuncSetAttribute(k_fused,   cudaFuncAttributeMaxDynamicSharedMemorySize, F_SMEM_BYTES);

    __half* d_xhc; cudaGetSymbolAddress((void**)&d_xhc, g_xhc);
    __half* d_xth; cudaGetSymbolAddress((void**)&d_xth, g_xth);
    __half* d_eh;  cudaGetSymbolAddress((void**)&d_eh,  g_eh);
    __half* d_wh;  cudaGetSymbolAddress((void**)&d_wh,  g_wh);

    k_scan<<<Bdim, 512>>>(masks);
    k_gtrc<<<dim3(Hdim / 32, Sdim / 32, Bdim + 1), dim3(32, 8)>>>(
        inputs, d_xth, d_xhc,
        (const float4*)emb,  (uint4*)d_eh, Ldim * Hdim / 8,
        (const float4*)wkey, (uint4*)d_wh, Hdim * Hdim / 8);
    k_keyproj<<<dim3(6, 64, 1), 256, K1_SMEM_BYTES>>>(d_xhc, d_wh);
    k_fused<<<dim3(Ldim / 64, Bdim), 512, F_SMEM_BYTES>>>(d_eh, d_xth, out);
}

// round 17
// speedup vs baseline: 1.4092x; 1.0293x over previous
#include <cuda_runtime.h>
#include <cuda_fp16.h>
#include <cstdint>

#define Bdim 8
#define Sdim 512
#define Hdim 768
#define Ldim 8192

// scratch (static device globals: allocation-free)
__device__ __half g_xhc[Bdim * Sdim * Hdim];                // gathered-compacted inputs fp16 [B,j,H]
__device__ __half g_xth[Bdim * Hdim * Sdim];                // gathered-compacted inputs^T [B,H,j] fp16
__device__ __half g_eh[Ldim * Hdim];                        // label_embedding fp16
__device__ __half g_wh[Hdim * Hdim];                        // W_key fp16
__device__ __half g_akh[Bdim * Sdim * Hdim];                // attn_key fp16 (compacted rows)
__device__ int    g_idx[Bdim * Sdim];                       // compaction index per batch
__device__ int    g_nv[Bdim];                               // valid count per batch

// ---------------- PTX helpers ----------------
__device__ __forceinline__ void mma_f16(float* c, const uint32_t* a, const uint32_t* b) {
    asm volatile(
        "mma.sync.aligned.m16n8k16.row.col.f32.f16.f16.f32 "
        "{%0,%1,%2,%3}, {%4,%5,%6,%7}, {%8,%9}, {%0,%1,%2,%3};\n"
        : "+f"(c[0]), "+f"(c[1]), "+f"(c[2]), "+f"(c[3])
        : "r"(a[0]), "r"(a[1]), "r"(a[2]), "r"(a[3]), "r"(b[0]), "r"(b[1]));
}

__device__ __forceinline__ void ldsm_x4(uint32_t& r0, uint32_t& r1, uint32_t& r2,
                                        uint32_t& r3, uint32_t addr) {
    asm volatile("ldmatrix.sync.aligned.m8n8.x4.shared.b16 {%0,%1,%2,%3}, [%4];"
                 : "=r"(r0), "=r"(r1), "=r"(r2), "=r"(r3) : "r"(addr));
}

__device__ __forceinline__ void cp16(uint32_t s, const void* g) {
    asm volatile("cp.async.cg.shared.global [%0], [%1], 16;\n" :: "r"(s), "l"(g));
}
__device__ __forceinline__ void cp_commit() { asm volatile("cp.async.commit_group;\n"); }
__device__ __forceinline__ void cp_wait1()  { asm volatile("cp.async.wait_group 1;\n"); }
__device__ __forceinline__ void cp_wait0()  { asm volatile("cp.async.wait_group 0;\n"); }

// ---------------- mask scan (with inline dtype detection) ----------------
__global__ void k_scan(const void* __restrict__ masks) {
    __shared__ int sc[512];
    int b = blockIdx.x, t = threadIdx.x;
    const unsigned* mw = (const unsigned*)masks;
    int bad = (mw[t * 2] > 1u) || (mw[t * 2 + 1] > 1u);
    int is32 = __syncthreads_or(bad) ? 0 : 1;
    unsigned v = is32 ? (unsigned)((const int*)masks)[b * Sdim + t]
                      : (unsigned)((const unsigned char*)masks)[b * Sdim + t];
    int m = v ? 1 : 0;
    sc[t] = m;
    __syncthreads();
    for (int off = 1; off < 512; off <<= 1) {
        int x = (t >= off) ? sc[t - off] : 0;
        __syncthreads();
        sc[t] += x;
        __syncthreads();
    }
    int nv = sc[511];
    if (m) g_idx[b * Sdim + sc[t] - 1] = t;
    if (t >= nv) g_idx[b * Sdim + t] = 0;
    if (t == 0) g_nv[b] = nv;
}

// ---- merged gather-transpose-convert + emb/wkey fp32->fp16 conversion ----
__global__ void k_gtrc(const float* __restrict__ X, __half* __restrict__ XT,
                       __half* __restrict__ XC,
                       const float4* __restrict__ s1, uint4* __restrict__ d1, int n1,
                       const float4* __restrict__ s2, uint4* __restrict__ d2, int n2) {
    if (blockIdx.z == Bdim) {
        int lb = blockIdx.x + gridDim.x * blockIdx.y;
        int t  = threadIdx.y * 32 + threadIdx.x;
        int i = lb * 256 + t;
        int stride = gridDim.x * gridDim.y * 256;
        for (; i < n1 + n2; i += stride) {
            const float4* src = (i < n1) ? s1 : s2;
            uint4* dst = (i < n1) ? d1 : d2;
            int j = (i < n1) ? i : i - n1;
            float4 a = src[2 * j], bq = src[2 * j + 1];
            __half2 h0 = __floats2half2_rn(a.x, a.y);
            __half2 h1 = __floats2half2_rn(a.z, a.w);
            __half2 h2 = __floats2half2_rn(bq.x, bq.y);
            __half2 h3 = __floats2half2_rn(bq.z, bq.w);
            uint4 o;
            o.x = *(uint32_t*)&h0; o.y = *(uint32_t*)&h1;
            o.z = *(uint32_t*)&h2; o.w = *(uint32_t*)&h3;
            dst[j] = o;
        }
        return;
    }
    __shared__ float t[32][33];
    int b = blockIdx.z;
    int j0 = blockIdx.y * 32, h0 = blockIdx.x * 32;
    int x = threadIdx.x, y = threadIdx.y;  // 32 x 8
    const float* srcb = X + (size_t)b * Sdim * Hdim;
#pragma unroll
    for (int i = 0; i < 32; i += 8) {
        int s = g_idx[b * Sdim + j0 + y + i];
        float v = srcb[(size_t)s * Hdim + h0 + x];
        t[y + i][x] = v;
        XC[((size_t)b * Sdim + j0 + y + i) * Hdim + h0 + x] = __float2half_rn(v);
    }
    __syncthreads();
    __half* dst = XT + ((size_t)b * Hdim + h0) * Sdim + j0;
#pragma unroll
    for (int i = 0; i < 32; i += 8)
        dst[(size_t)(y + i) * Sdim + x] = __float2half_rn(t[x][y + i]);
}

#define RS 72   // BK=64 row stride (halves); stride 144B -> LDSM conflict-free

// ---------------- Kernel 1: attn_key(compacted) = xhc @ W_key^T ----------------
#define K1_ASTG (64 * RS)
#define K1_BSTG (128 * RS)
#define K1_SMEM_BYTES (2 * (K1_ASTG + K1_BSTG) * 2)

__global__ __launch_bounds__(256) void k_keyproj(const __half* __restrict__ A,
                                                 const __half* __restrict__ W) {
    const int m0 = blockIdx.y * 64, n0 = blockIdx.x * 128;
    {
        int b = m0 >> 9, j0 = m0 & 511;
        if (j0 >= g_nv[b]) return;
    }
    extern __shared__ __align__(16) float smem[];
    uint32_t sb  = (uint32_t)__cvta_generic_to_shared(smem);
    const uint32_t sbA = sb;
    const uint32_t sbB = sb + 2u * K1_ASTG * 2u;

    const int tid  = threadIdx.x;
    const int lane = tid & 31, wid = tid >> 5;
    const int wm = wid & 1, wn = wid >> 1;   // 2 x 4
    const int tg = lane & 3, gid = lane >> 2;

    const int a_row = lane & 15, a_kh = (lane >> 4) << 3;
    const int b_row = ((lane >> 4) << 3) + (lane & 7), b_kh = ((lane >> 3) & 1) << 3;

    float acc[2][4][4];
#pragma unroll
    for (int i = 0; i < 2; i++)
#pragma unroll
        for (int j = 0; j < 4; j++)
#pragma unroll
            for (int r = 0; r < 4; r++) acc[i][j][r] = 0.f;

    auto fill = [&](int st, int kt) {
#pragma unroll
        for (int i = 0; i < 2; i++) {
            int idx = tid + i * 256;
            int r = idx >> 3, c = (idx & 7) * 8;
            cp16(sbA + (uint32_t)(st * K1_ASTG + r * RS + c) * 2u,
                 A + (size_t)(m0 + r) * Hdim + kt * 64 + c);
        }
#pragma unroll
        for (int i = 0; i < 4; i++) {
            int idx = tid + i * 256;
            int r = idx >> 3, c = (idx & 7) * 8;
            cp16(sbB + (uint32_t)(st * K1_BSTG + r * RS + c) * 2u,
                 W + (size_t)(n0 + r) * Hdim + kt * 64 + c);
        }
        cp_commit();
    };

    const int KT = Hdim / 64;  // 12
    fill(0, 0);
#pragma unroll 1
    for (int kt = 0; kt < KT; ++kt) {
        int cur = kt & 1;
        if (kt + 1 < KT) { fill(cur ^ 1, kt + 1); cp_wait1(); }
        else             { cp_wait0(); }
        __syncthreads();
        const uint32_t aBase = sbA + (uint32_t)(cur * K1_ASTG) * 2u;
        const uint32_t bBase = sbB + (uint32_t)(cur * K1_BSTG) * 2u;
#pragma unroll
        for (int kk = 0; kk < 4; ++kk) {
            uint32_t af[2][4], bf[4][2];
#pragma unroll
            for (int mt = 0; mt < 2; ++mt)
                ldsm_x4(af[mt][0], af[mt][1], af[mt][2], af[mt][3],
                        aBase + (uint32_t)(((wm * 32 + mt * 16 + a_row) * RS + kk * 16 + a_kh) * 2));
#pragma unroll
            for (int p = 0; p < 2; ++p)
                ldsm_x4(bf[2 * p][0], bf[2 * p][1], bf[2 * p + 1][0], bf[2 * p + 1][1],
                        bBase + (uint32_t)(((wn * 32 + p * 16 + b_row) * RS + kk * 16 + b_kh) * 2));
#pragma unroll
            for (int mt = 0; mt < 2; ++mt)
#pragma unroll
                for (int nt = 0; nt < 4; ++nt)
                    mma_f16(acc[mt][nt], af[mt], bf[nt]);
        }
        __syncthreads();
    }
#pragma unroll
    for (int mt = 0; mt < 2; ++mt) {
        int r = m0 + wm * 32 + mt * 16 + gid;
#pragma unroll
        for (int nt = 0; nt < 4; ++nt) {
            int c = n0 + wn * 32 + nt * 8 + tg * 2;
            *(__half2*)(&g_akh[(size_t)r * Hdim + c]) =
                __floats2half2_rn(acc[mt][nt][0], acc[mt][nt][1]);
            *(__half2*)(&g_akh[(size_t)(r + 8) * Hdim + c]) =
                __floats2half2_rn(acc[mt][nt][2], acc[mt][nt][3]);
        }
    }
}

// ---------------- Fused Kernel (compacted S, 512 threads, BK=64) -----------
// Phase 1: 3-stage single-barrier pipeline (B stages 320 rows, 2 column passes).
// Phase 2: flattened (ht,kt) single 3-stage pipeline; first 2 stages prefetched
//          under the softmax; epilogues overlap next-tile fills.
#define P_RS 520
#define F1_AST (64 * RS)
#define F1_BST (320 * RS)
#define F2_ST  (256 * RS)
#define F_XT_BYTE (64 * P_RS * 2)
#define F_RED_BYTE (F_XT_BYTE + 3 * F2_ST * 2)
#define F_SMEM_BYTES (F_RED_BYTE + 64 * 8 * 4 + 16)

__global__ __launch_bounds__(512) void k_fused(const __half* __restrict__ E,
                                               const __half* __restrict__ XT,
                                               float* __restrict__ O) {
    extern __shared__ __align__(16) float smem[];
    uint32_t sb = (uint32_t)__cvta_generic_to_shared(smem);
    float* red = (float*)((char*)smem + F_RED_BYTE);

    const int tid  = threadIdx.x;
    const int lane = tid & 31, wid = tid >> 5;
    const int wm = wid & 1, wn = wid >> 1;  // 2 x 8
    const int tg = lane & 3, gid = lane >> 2;
    const int b  = blockIdx.y;
    const int m0 = blockIdx.x * 64;
    const __half* Bt = g_akh + (size_t)b * Sdim * Hdim;   // compacted rows
    const int nv = g_nv[b];

    const int a_row = lane & 15, a_kh = (lane >> 4) << 3;
    const int b_row = ((lane >> 4) << 3) + (lane & 7), b_kh = ((lane >> 3) & 1) << 3;

    const uint32_t sbA1 = sb;
    const uint32_t sbB1 = sb + 3u * F1_AST * 2u;

    // ================= Phase 1: scores + softmax =================
    float acc[2][8][4];
#pragma unroll
    for (int i = 0; i < 2; i++)
#pragma unroll
        for (int j = 0; j < 8; j++)
#pragma unroll
            for (int r = 0; r < 4; r++) acc[i][j][r] = 0.f;

    const int KT = Hdim / 64;  // 12
#pragma unroll 1
    for (int pass = 0; pass < 2; ++pass) {
        int cb = pass * 320;
        if (cb >= nv) break;
        int cbe  = (nv < cb + 320) ? nv : (cb + 320);
        int rows = cbe - cb;

        auto fill1 = [&](int st, int kt) {
            {
                int r = tid >> 3, c = (tid & 7) * 8;
                cp16(sbA1 + (uint32_t)(st * F1_AST + r * RS + c) * 2u,
                     E + (size_t)(m0 + r) * Hdim + kt * 64 + c);
            }
#pragma unroll 1
            for (int i = 0; i < 5; i++) {
                if (i * 64 >= rows) break;
                int idx = tid + i * 512;
                int r = idx >> 3, c = (idx & 7) * 8;
                if (r < rows)
                    cp16(sbB1 + (uint32_t)(st * F1_BST + r * RS + c) * 2u,
                         Bt + (size_t)(cb + r) * Hdim + kt * 64 + c);
            }
            cp_commit();
        };

        fill1(0, 0);
        fill1(1, 1);
        cp_wait1();
        __syncthreads();

#pragma unroll 1
        for (int kt = 0; kt < KT; ++kt) {
            int cur = kt % 3;
            const uint32_t aBase = sbA1 + (uint32_t)(cur * F1_AST) * 2u;
            const uint32_t bBase = sbB1 + (uint32_t)(cur * F1_BST) * 2u;
#pragma unroll
            for (int kk = 0; kk < 4; ++kk) {
                uint32_t af[2][4], bf[8][2];
#pragma unroll
                for (int mt = 0; mt < 2; ++mt)
                    ldsm_x4(af[mt][0], af[mt][1], af[mt][2], af[mt][3],
                            aBase + (uint32_t)(((wm * 32 + mt * 16 + a_row) * RS + kk * 16 + a_kh) * 2));
#pragma unroll
                for (int p = 0; p < 4; ++p) {
                    int c0 = (8 * p + wn) * 16;
                    if (c0 >= cb && c0 < cbe) {
                        ldsm_x4(bf[2 * p][0], bf[2 * p][1], bf[2 * p + 1][0], bf[2 * p + 1][1],
                                bBase + (uint32_t)(((c0 - cb + b_row) * RS + kk * 16 + b_kh) * 2));
#pragma unroll
                        for (int mt = 0; mt < 2; ++mt) {
                            mma_f16(acc[mt][2 * p],     af[mt], bf[2 * p]);
                            mma_f16(acc[mt][2 * p + 1], af[mt], bf[2 * p + 1]);
                        }
                    }
                }
            }
            if (kt + 2 < KT) fill1((kt + 2) % 3, kt + 2);
            if (kt + 1 < KT) { if (kt + 2 < KT) cp_wait1(); else cp_wait0(); }
            __syncthreads();
        }
    }
    // all phase-1 smem reads done across the CTA before XT prefetch overwrites it
    __syncthreads();

    // -------- phase-2 prefetch (overlaps softmax below) --------
    const uint32_t pB   = sb;
    const uint32_t sbXT = sb + (uint32_t)F_XT_BYTE;
    const int KT2 = (nv + 63) >> 6;   // >= 1
    const int NS  = 3 * KT2;
    int fht = 0, fkt = 0;
    auto fill2 = [&](int st) {
        const __half* Xg = XT + ((size_t)b * Hdim + fht * 256) * Sdim;
#pragma unroll
        for (int i = 0; i < 4; i++) {
            int idx = tid + i * 512;
            int r = idx >> 3, c = (idx & 7) * 8;
            cp16(sbXT + (uint32_t)(st * F2_ST + r * RS + c) * 2u,
                 Xg + (size_t)r * Sdim + fkt * 64 + c);
        }
        cp_commit();
        if (++fkt == KT2) { fkt = 0; ++fht; }
    };
    fill2(0);
    if (NS > 1) fill2(1);

    // ---------------- softmax (overlapped with prefetch) ----------------
    float mx[4] = {-1e30f, -1e30f, -1e30f, -1e30f};
#pragma unroll
    for (int mt = 0; mt < 2; ++mt)
#pragma unroll
        for (int nt = 0; nt < 8; ++nt) {
            int col = (8 * (nt >> 1) + wn) * 16 + (nt & 1) * 8 + tg * 2;
            if (col >= nv)     { acc[mt][nt][0] = -1e30f; acc[mt][nt][2] = -1e30f; }
            if (col + 1 >= nv) { acc[mt][nt][1] = -1e30f; acc[mt][nt][3] = -1e30f; }
            mx[mt * 2]     = fmaxf(mx[mt * 2],     fmaxf(acc[mt][nt][0], acc[mt][nt][1]));
            mx[mt * 2 + 1] = fmaxf(mx[mt * 2 + 1], fmaxf(acc[mt][nt][2], acc[mt][nt][3]));
        }
#pragma unroll
    for (int j = 0; j < 4; ++j) {
        mx[j] = fmaxf(mx[j], __shfl_xor_sync(0xffffffffu, mx[j], 1));
        mx[j] = fmaxf(mx[j], __shfl_xor_sync(0xffffffffu, mx[j], 2));
    }
    if (tg == 0) {
#pragma unroll
        for (int j = 0; j < 4; ++j) {
            int rl = wm * 32 + (j >> 1) * 16 + (j & 1) * 8 + gid;
            red[rl * 8 + wn] = mx[j];
        }
    }
    __syncthreads();
    float gmx[4];
#pragma unroll
    for (int j = 0; j < 4; ++j) {
        int rl = wm * 32 + (j >> 1) * 16 + (j & 1) * 8 + gid;
        float m = -1e30f;
#pragma unroll
        for (int w = 0; w < 8; ++w) m = fmaxf(m, red[rl * 8 + w]);
        gmx[j] = m;
    }
    __syncthreads();

    float sme[4] = {0.f, 0.f, 0.f, 0.f};
#pragma unroll
    for (int mt = 0; mt < 2; ++mt)
#pragma unroll
        for (int nt = 0; nt < 8; ++nt) {
            float e0 = __expf(acc[mt][nt][0] - gmx[mt * 2]);
            float e1 = __expf(acc[mt][nt][1] - gmx[mt * 2]);
            float e2 = __expf(acc[mt][nt][2] - gmx[mt * 2 + 1]);
            float e3 = __expf(acc[mt][nt][3] - gmx[mt * 2 + 1]);
            acc[mt][nt][0] = e0; acc[mt][nt][1] = e1;
            acc[mt][nt][2] = e2; acc[mt][nt][3] = e3;
            sme[mt * 2]     += e0 + e1;
            sme[mt * 2 + 1] += e2 + e3;
        }
#pragma unroll
    for (int j = 0; j < 4; ++j) {
        sme[j] += __shfl_xor_sync(0xffffffffu, sme[j], 1);
        sme[j] += __shfl_xor_sync(0xffffffffu, sme[j], 2);
    }
    if (tg == 0) {
#pragma unroll
        for (int j = 0; j < 4; ++j) {
            int rl = wm * 32 + (j >> 1) * 16 + (j & 1) * 8 + gid;
            red[rl * 8 + wn] = sme[j];
        }
    }
    __syncthreads();
    float inv[4];
#pragma unroll
    for (int j = 0; j < 4; ++j) {
        int rl = wm * 32 + (j >> 1) * 16 + (j & 1) * 8 + gid;
        float s = 0.f;
#pragma unroll
        for (int w = 0; w < 8; ++w) s += red[rl * 8 + w];
        inv[j] = 1.f / s;
    }

    // probs -> smem fp16 (region disjoint from XT stage buffers)
    __half* probs = (__half*)smem;
#pragma unroll
    for (int mt = 0; mt < 2; ++mt) {
        int r0 = wm * 32 + mt * 16 + gid;
        int r1 = r0 + 8;
#pragma unroll
        for (int nt = 0; nt < 8; ++nt) {
            int col = (8 * (nt >> 1) + wn) * 16 + (nt & 1) * 8 + tg * 2;
            *(__half2*)(&probs[r0 * P_RS + col]) =
                __floats2half2_rn(acc[mt][nt][0] * inv[mt * 2], acc[mt][nt][1] * inv[mt * 2]);
            *(__half2*)(&probs[r1 * P_RS + col]) =
                __floats2half2_rn(acc[mt][nt][2] * inv[mt * 2 + 1], acc[mt][nt][3] * inv[mt * 2 + 1]);
        }
    }
    // ensure stage0 (and stage1) loads landed; probs visible to all
    if (NS > 2) cp_wait1(); else cp_wait0();
    __syncthreads();

    // ================= Phase 2: flattened (ht,kt) pipeline ============
    float acc2[2][4][4];
#pragma unroll
    for (int i = 0; i < 2; i++)
#pragma unroll
        for (int j = 0; j < 4; j++)
#pragma unroll
            for (int r = 0; r < 4; r++) acc2[i][j][r] = 0.f;

    int ht = 0, kt = 0;
#pragma unroll 1
    for (int s = 0; s < NS; ++s) {
        int cur = s % 3;
        const uint32_t xBase = sbXT + (uint32_t)(cur * F2_ST) * 2u;
#pragma unroll
        for (int kk = 0; kk < 4; ++kk) {
            uint32_t af[2][4], bf[4][2];
#pragma unroll
            for (int mt = 0; mt < 2; ++mt)
                ldsm_x4(af[mt][0], af[mt][1], af[mt][2], af[mt][3],
                        pB + (uint32_t)(((wm * 32 + mt * 16 + a_row) * P_RS +
                                         kt * 64 + kk * 16 + a_kh) * 2));
#pragma unroll
            for (int p = 0; p < 2; ++p)
                ldsm_x4(bf[2 * p][0], bf[2 * p][1], bf[2 * p + 1][0], bf[2 * p + 1][1],
                        xBase + (uint32_t)(((wn * 32 + p * 16 + b_row) * RS + kk * 16 + b_kh) * 2));
#pragma unroll
            for (int mt = 0; mt < 2; ++mt)
#pragma unroll
                for (int nt = 0; nt < 4; ++nt)
                    mma_f16(acc2[mt][nt], af[mt], bf[nt]);
        }
        if (s + 2 < NS) fill2((s + 2) % 3);

        if (kt == KT2 - 1) {
            // epilogue for this H-third (overlaps in-flight fills)
#pragma unroll
            for (int mt = 0; mt < 2; ++mt) {
                int r = m0 + wm * 32 + mt * 16 + gid;
                size_t base0 = ((size_t)b * Ldim + r) * Hdim;
                size_t base1 = ((size_t)b * Ldim + r + 8) * Hdim;
#pragma unroll
                for (int nt = 0; nt < 4; ++nt) {
                    int c = ht * 256 + wn * 32 + nt * 8 + tg * 2;
                    *(float2*)(&O[base0 + c]) = make_float2(acc2[mt][nt][0], acc2[mt][nt][1]);
                    *(float2*)(&O[base1 + c]) = make_float2(acc2[mt][nt][2], acc2[mt][nt][3]);
                }
            }
#pragma unroll
            for (int i = 0; i < 2; i++)
#pragma unroll
                for (int j = 0; j < 4; j++)
#pragma unroll
                    for (int r = 0; r < 4; r++) acc2[i][j][r] = 0.f;
        }
        if (++kt == KT2) { kt = 0; ++ht; }

        if (s + 1 < NS) {
            if (s + 2 < NS) cp_wait1(); else cp_wait0();
            __syncthreads();
        }
    }
}

// ---------------- launcher ----------------
extern "C" void kernel_launch(void* const* d_in, const int* in_sizes, int n_in,
                              void* d_out, int out_size) {
    const float* inputs = (const float*)d_in[0];
    const void*  masks  = d_in[1];
    const float* emb    = (const float*)d_in[2];
    const float* wkey   = (const float*)d_in[3];
    float* out = (float*)d_out;
    (void)in_sizes; (void)n_in; (void)out_size;

    cudaFuncSetAttribute(k_keyproj, cudaFuncAttributeMaxDynamicSharedMemorySize, K1_SMEM_BYTES);
    cudaFuncSetAttribute(k_fused,   cudaFuncAttributeMaxDynamicSharedMemorySize, F_SMEM_BYTES);

    __half* d_xhc; cudaGetSymbolAddress((void**)&d_xhc, g_xhc);
    __half* d_xth; cudaGetSymbolAddress((void**)&d_xth, g_xth);
    __half* d_eh;  cudaGetSymbolAddress((void**)&d_eh,  g_eh);
    __half* d_wh;  cudaGetSymbolAddress((void**)&d_wh,  g_wh);

    k_scan<<<Bdim, 512>>>(masks);
    k_gtrc<<<dim3(Hdim / 32, Sdim / 32, Bdim + 1), dim3(32, 8)>>>(
        inputs, d_xth, d_xhc,
        (const float4*)emb,  (uint4*)d_eh, Ldim * Hdim / 8,
        (const float4*)wkey, (uint4*)d_wh, Hdim * Hdim / 8);
    k_keyproj<<<dim3(6, 64, 1), 256, K1_SMEM_BYTES>>>(d_xhc, d_wh);
    k_fused<<<dim3(Ldim / 64, Bdim), 512, F_SMEM_BYTES>>>(d_eh, d_xth, out);
}